// round 11
// baseline (speedup 1.0000x reference)
#include <cuda_runtime.h>
#include <cuda_bf16.h>
#include <cstdint>

// ---------------------------------------------------------------------------
// GAE 4-layer GCN autoencoder: algebraic fusion + CSR gather + tf32 mma GEMMs,
// with stream-forked preprocessing (CSR chain || weight+P chain) and a
// single-pass register scan.
// ---------------------------------------------------------------------------

#define N_NODES 20000
#define IN_DIM  1024
#define HID_DIM 512
#define OUT_DIM 128
#define N_EDGES 160000

__device__ alignas(16) float g_T[(size_t)N_NODES * OUT_DIM];
__device__ alignas(16) float g_H[(size_t)N_NODES * OUT_DIM];
__device__ alignas(16) float g_W21[(size_t)OUT_DIM * IN_DIM];    // tf32-rounded
__device__ alignas(16) float g_W21t[(size_t)IN_DIM * OUT_DIM];   // tf32-rounded
__device__ alignas(16) float g_Ht[(size_t)OUT_DIM * OUT_DIM];    // head1^T tf32
__device__ alignas(16) float g_u2[OUT_DIM];
__device__ alignas(16) float g_u4[IN_DIM];
__device__ float g_dinv[N_NODES];
__device__ float g_sn[N_NODES];
__device__ float g_c[N_NODES];
__device__ int   g_cnt[N_NODES];
__device__ int   g_off[N_NODES + 1];
__device__ int   g_cur[N_NODES];
__device__ int2  g_adj[N_EDGES];
__device__ int   g_is64;

// pointer selector: 0 ext, 1 g_T, 2 g_H, 3 g_W21, 4 g_W21t, 5 g_Ht
template <int SEL>
__device__ __forceinline__ float* pick(float* ext) {
    if (SEL == 1) return g_T;
    if (SEL == 2) return g_H;
    if (SEL == 3) return g_W21;
    if (SEL == 4) return g_W21t;
    if (SEL == 5) return g_Ht;
    return ext;
}
template <int SEL>
__device__ __forceinline__ const float* pickc(const float* ext) {
    if (SEL == 1) return g_T;
    if (SEL == 2) return g_H;
    if (SEL == 3) return g_W21;
    if (SEL == 4) return g_W21t;
    if (SEL == 5) return g_Ht;
    return ext;
}

__device__ __forceinline__ unsigned f2t(float x) {
    unsigned u;
    asm("cvt.rna.tf32.f32 %0, %1;" : "=r"(u) : "f"(x));
    return u;
}
__device__ __forceinline__ float f2tf(float x) { return __uint_as_float(f2t(x)); }

// ---------------------------------------------------------------------------
// probe dtype + zero counters (fused)
// ---------------------------------------------------------------------------
__global__ void k_pre(const int* __restrict__ ei32, int n) {
    int i = blockIdx.x * blockDim.x + threadIdx.x;
    if (i == 0) {
        int z = (ei32[1] == 0) & (ei32[3] == 0) & (ei32[5] == 0) &
                (ei32[7] == 0) & (ei32[9] == 0) & (ei32[11] == 0);
        g_is64 = z;
    }
    if (i < n) g_cnt[i] = 0;
}

__device__ __forceinline__ int load_idx(const void* ei, int e_cnt, int row, int e) {
    if (g_is64) return (int)((const long long*)ei)[(size_t)row * e_cnt + e];
    return ((const int*)ei)[(size_t)row * e_cnt + e];
}

__global__ void k_count(const void* __restrict__ ei, int e_cnt, int n) {
    int e = blockIdx.x * blockDim.x + threadIdx.x;
    if (e < e_cnt) {
        int d = load_idx(ei, e_cnt, 1, e);
        if ((unsigned)d < (unsigned)n) atomicAdd(&g_cnt[d], 1);
    }
}

// ---------------------------------------------------------------------------
// Single-pass scan (1024 threads, SCAN_CHUNK elems/thread in registers)
// also computes dinv / sn.  Produces g_off (exclusive+1) and g_cur.
// ---------------------------------------------------------------------------
#define SCAN_CHUNK ((N_NODES + 1023) / 1024)

__global__ __launch_bounds__(1024)
void k_scan(int n) {
    int tid = threadIdx.x;
    int lane = tid & 31, wid = tid >> 5;
    int base = tid * SCAN_CHUNK;
    int vloc[SCAN_CHUNK];
    int s = 0;
#pragma unroll
    for (int j = 0; j < SCAN_CHUNK; j++) {
        int i = base + j;
        int v = (i < n) ? g_cnt[i] : 0;
        vloc[j] = v;
        s += v;
    }
    int x = s;
#pragma unroll
    for (int d = 1; d < 32; d <<= 1) {
        int y = __shfl_up_sync(0xFFFFFFFFu, x, d);
        if (lane >= d) x += y;
    }
    __shared__ int ws[32];
    if (lane == 31) ws[wid] = x;
    __syncthreads();
    if (wid == 0) {
        int w = ws[lane];
#pragma unroll
        for (int d = 1; d < 32; d <<= 1) {
            int y = __shfl_up_sync(0xFFFFFFFFu, w, d);
            if (lane >= d) w += y;
        }
        ws[lane] = w;
    }
    __syncthreads();
    int excl = x - s + ((wid > 0) ? ws[wid - 1] : 0);
    if (tid == 0) g_off[0] = 0;
#pragma unroll
    for (int j = 0; j < SCAN_CHUNK; j++) {
        int i = base + j;
        if (i < n) {
            g_cur[i] = excl;
            excl += vloc[j];
            g_off[i + 1] = excl;
            float r = rsqrtf((float)(vloc[j] + 1));
            g_dinv[i] = r;
            g_sn[i] = r * r;
        }
    }
}

__global__ void k_fill(const void* __restrict__ ei, int e_cnt, int n) {
    int e = blockIdx.x * blockDim.x + threadIdx.x;
    if (e < e_cnt) {
        int s = load_idx(ei, e_cnt, 0, e);
        int d = load_idx(ei, e_cnt, 1, e);
        if ((unsigned)s >= (unsigned)n) s = 0;
        if ((unsigned)d >= (unsigned)n) d = 0;
        float w = g_dinv[s] * g_dinv[d];
        int pos = atomicAdd(&g_cur[d], 1);
        g_adj[pos] = make_int2(s, __float_as_int(w));
    }
}

// ---------------------------------------------------------------------------
// misc precomputes: u4 (blocks 0..3), u2 (block 4), head1^T tf32 (block 5)
// ---------------------------------------------------------------------------
__global__ void k_misc(const float* __restrict__ W1, const float* __restrict__ W2,
                       const float* __restrict__ b1, const float* __restrict__ b3,
                       const float* __restrict__ head1) {
    int bidx = blockIdx.x;
    if (bidx < 4) {
        int f = bidx * 256 + threadIdx.x;
        float s = 0.f;
        for (int k = 0; k < HID_DIM; k++) s += b3[k] * W1[(size_t)k * IN_DIM + f];
        g_u4[f] = s;
    } else if (bidx == 4) {
        if (threadIdx.x < OUT_DIM) {
            int o = threadIdx.x;
            float s = 0.f;
            for (int k = 0; k < HID_DIM; k++) s += W2[(size_t)o * HID_DIM + k] * b1[k];
            g_u2[o] = s;
        }
    } else {
        for (int idx = threadIdx.x; idx < OUT_DIM * OUT_DIM; idx += 256) {
            int r = idx >> 7, c = idx & 127;
            g_Ht[(size_t)c * OUT_DIM + r] = f2tf(head1[idx]);
        }
    }
}

// ---------------------------------------------------------------------------
// W21 = W2 @ W1 (fp32 FFMA), epilogue writes tf32-rounded W21 and W21^T.
// ---------------------------------------------------------------------------
__global__ __launch_bounds__(256)
void k_w21(const float* __restrict__ A, const float* __restrict__ B) {
    __shared__ float As[8][64];
    __shared__ float Bs[8][128];
    const int bx = blockIdx.x;
    const int by = blockIdx.y;
    const int tid = threadIdx.x;
    const int tcol = tid % 16;
    const int trow = tid / 16;

    float acc[4][8];
#pragma unroll
    for (int i = 0; i < 4; i++)
#pragma unroll
        for (int j = 0; j < 8; j++) acc[i][j] = 0.0f;

    for (int k0 = 0; k0 < HID_DIM; k0 += 8) {
        if (tid < 128) {
            int aRow = tid >> 1;
            int aCol = (tid & 1) << 2;
            int m = by * 64 + aRow;
            float4 av = *(const float4*)(A + (size_t)m * HID_DIM + k0 + aCol);
            As[aCol + 0][aRow] = av.x;
            As[aCol + 1][aRow] = av.y;
            As[aCol + 2][aRow] = av.z;
            As[aCol + 3][aRow] = av.w;
        }
        {
            int kk = tid >> 5;
            int nn = (tid & 31) << 2;
            float4 bv = *(const float4*)(B + (size_t)(k0 + kk) * IN_DIM + bx * 128 + nn);
            *(float4*)&Bs[kk][nn] = bv;
        }
        __syncthreads();
#pragma unroll
        for (int k = 0; k < 8; k++) {
            float ra[4], rb[8];
#pragma unroll
            for (int i = 0; i < 4; i++) ra[i] = As[k][trow * 4 + i];
#pragma unroll
            for (int j = 0; j < 8; j++) rb[j] = Bs[k][tcol * 8 + j];
#pragma unroll
            for (int i = 0; i < 4; i++)
#pragma unroll
                for (int j = 0; j < 8; j++) acc[i][j] += ra[i] * rb[j];
        }
        __syncthreads();
    }
#pragma unroll
    for (int i = 0; i < 4; i++) {
        int m = by * 64 + trow * 4 + i;
#pragma unroll
        for (int j = 0; j < 8; j++) {
            int col = bx * 128 + tcol * 8 + j;
            float w = f2tf(acc[i][j]);
            g_W21[(size_t)m * IN_DIM + col]  = w;
            g_W21t[(size_t)col * OUT_DIM + m] = w;
        }
    }
}

// ---------------------------------------------------------------------------
// tf32 tensor-core GEMM (TN form), register-prefetch pipelined.
// ---------------------------------------------------------------------------
template <int ASEL, int BSEL, int CSEL, int CORR4, int BMv>
__global__ __launch_bounds__(256)
void k_mma(int M, int Nn, int K,
           const float* __restrict__ Aext,
           const float* __restrict__ Bext,
           float* __restrict__ Cext,
           const float* __restrict__ bias) {
    constexpr int MT  = BMv / 32;
    constexpr int AR4 = (BMv * 32) / (256 * 4);
    const float* A = pickc<ASEL>(Aext);
    const float* B = pickc<BSEL>(Bext);
    float*       C = pick<CSEL>(Cext);

    __shared__ float As[BMv][36];
    __shared__ float Bs[128][36];

    const int tid  = threadIdx.x;
    const int lane = tid & 31;
    const int wid  = tid >> 5;
    const int g    = lane >> 2;
    const int t    = lane & 3;
    const int wm   = (wid & 1) * (BMv / 2);
    const int wn   = (wid >> 1) * 32;
    const int bx   = blockIdx.x;
    const int by   = blockIdx.y;

    float4 ar[AR4], br[4];

    auto loadA = [&](int k0) {
#pragma unroll
        for (int i = 0; i < AR4; i++) {
            int f4 = tid + i * 256;
            int m  = f4 >> 3;
            int kq = (f4 & 7) << 2;
            int gm = by * BMv + m;
            ar[i] = (gm < M) ? *(const float4*)(A + (size_t)gm * K + k0 + kq)
                             : make_float4(0.f, 0.f, 0.f, 0.f);
        }
    };
    auto loadB = [&](int k0) {
#pragma unroll
        for (int i = 0; i < 4; i++) {
            int f4 = tid + i * 256;
            int nn = f4 >> 3;
            int kq = (f4 & 7) << 2;
            br[i] = *(const float4*)(B + (size_t)(bx * 128 + nn) * K + k0 + kq);
        }
    };
    auto storeA = [&]() {
#pragma unroll
        for (int i = 0; i < AR4; i++) {
            int f4 = tid + i * 256;
            int m  = f4 >> 3;
            int kq = (f4 & 7) << 2;
            float4 w;
            w.x = f2tf(ar[i].x); w.y = f2tf(ar[i].y);
            w.z = f2tf(ar[i].z); w.w = f2tf(ar[i].w);
            *(float4*)&As[m][kq] = w;
        }
    };
    auto storeB = [&]() {
#pragma unroll
        for (int i = 0; i < 4; i++) {
            int f4 = tid + i * 256;
            int nn = f4 >> 3;
            int kq = (f4 & 7) << 2;
            *(float4*)&Bs[nn][kq] = br[i];
        }
    };

    float c[MT][4][4];
#pragma unroll
    for (int i = 0; i < MT; i++)
#pragma unroll
        for (int j = 0; j < 4; j++)
#pragma unroll
            for (int r = 0; r < 4; r++) c[i][j][r] = 0.0f;

    const int nt = K / 32;
    loadA(0); loadB(0);
    storeA(); storeB();
    __syncthreads();

    for (int it = 0; it < nt; it++) {
        if (it + 1 < nt) { loadA((it + 1) * 32); loadB((it + 1) * 32); }

#pragma unroll
        for (int ks = 0; ks < 4; ks++) {
            unsigned a[MT][4], b[4][2];
            int kk = ks * 8 + t;
#pragma unroll
            for (int i = 0; i < MT; i++) {
                int mr = wm + i * 16 + g;
                a[i][0] = __float_as_uint(As[mr    ][kk    ]);
                a[i][1] = __float_as_uint(As[mr + 8][kk    ]);
                a[i][2] = __float_as_uint(As[mr    ][kk + 4]);
                a[i][3] = __float_as_uint(As[mr + 8][kk + 4]);
            }
#pragma unroll
            for (int j = 0; j < 4; j++) {
                int nr = wn + j * 8 + g;
                b[j][0] = __float_as_uint(Bs[nr][kk    ]);
                b[j][1] = __float_as_uint(Bs[nr][kk + 4]);
            }
#pragma unroll
            for (int i = 0; i < MT; i++)
#pragma unroll
                for (int j = 0; j < 4; j++) {
                    asm volatile(
                        "mma.sync.aligned.m16n8k8.row.col.f32.tf32.tf32.f32 "
                        "{%0,%1,%2,%3}, {%4,%5,%6,%7}, {%8,%9}, {%0,%1,%2,%3};"
                        : "+f"(c[i][j][0]), "+f"(c[i][j][1]),
                          "+f"(c[i][j][2]), "+f"(c[i][j][3])
                        : "r"(a[i][0]), "r"(a[i][1]), "r"(a[i][2]), "r"(a[i][3]),
                          "r"(b[j][0]), "r"(b[j][1]));
                }
        }
        __syncthreads();
        if (it + 1 < nt) {
            storeA(); storeB();
            __syncthreads();
        }
    }

#pragma unroll
    for (int j = 0; j < 4; j++) {
        int cn = bx * 128 + wn + j * 8 + t * 2;
        float e0 = bias ? bias[cn]     : 0.0f;
        float e1 = bias ? bias[cn + 1] : 0.0f;
        float u40 = CORR4 ? g_u4[cn]     : 0.0f;
        float u41 = CORR4 ? g_u4[cn + 1] : 0.0f;
#pragma unroll
        for (int i = 0; i < MT; i++) {
            int r0 = by * BMv + wm + i * 16 + g;
            if (r0 < M) {
                float a0 = c[i][j][0] + e0, a1 = c[i][j][1] + e1;
                if (CORR4) { float ci = g_c[r0]; a0 += ci * u40; a1 += ci * u41; }
                *(float2*)(C + (size_t)r0 * Nn + cn) = make_float2(a0, a1);
            }
            int r1 = r0 + 8;
            if (r1 < M) {
                float a2 = c[i][j][2] + e0, a3 = c[i][j][3] + e1;
                if (CORR4) { float ci = g_c[r1]; a2 += ci * u40; a3 += ci * u41; }
                *(float2*)(C + (size_t)r1 * Nn + cn) = make_float2(a2, a3);
            }
        }
    }
}

// ---------------------------------------------------------------------------
// Aggregation (warp-per-node CSR gather), exact fp32.
// ---------------------------------------------------------------------------
template <int SSEL, int DSEL, int CORR, int WRC>
__global__ __launch_bounds__(256)
void k_agg(const float* __restrict__ Sext,
           float* __restrict__ Dext,
           const float* __restrict__ b,
           int n) {
    int gw = (blockIdx.x * 256 + threadIdx.x) >> 5;
    if (gw >= n) return;
    int lane = threadIdx.x & 31;
    const float* S = pickc<SSEL>(Sext);
    float*       D = pick<DSEL>(Dext);

    int beg = g_off[gw];
    int end = g_off[gw + 1];
    float sn = g_sn[gw];
    float4 v = *(const float4*)(S + (size_t)gw * OUT_DIM + lane * 4);
    float4 acc = make_float4(sn * v.x, sn * v.y, sn * v.z, sn * v.w);
    float cacc = sn;

    for (int p = beg; p < end; p++) {
        int2 pr = g_adj[p];
        float w = __int_as_float(pr.y);
        if (WRC) cacc += w;
        float4 u = *(const float4*)(S + (size_t)pr.x * OUT_DIM + lane * 4);
        acc.x += w * u.x;
        acc.y += w * u.y;
        acc.z += w * u.z;
        acc.w += w * u.w;
    }

    if (WRC && lane == 0) g_c[gw] = cacc;

    if (CORR) {
        float ci = g_c[gw];
        int f = lane * 4;
        acc.x += ci * g_u2[f + 0] + b[f + 0];
        acc.y += ci * g_u2[f + 1] + b[f + 1];
        acc.z += ci * g_u2[f + 2] + b[f + 2];
        acc.w += ci * g_u2[f + 3] + b[f + 3];
    }
    *(float4*)(D + (size_t)gw * OUT_DIM + lane * 4) = acc;
}

// ---------------------------------------------------------------------------
static inline int ceil_div(int a, int b) { return (a + b - 1) / b; }

extern "C" void kernel_launch(void* const* d_in, const int* in_sizes, int n_in,
                              void* d_out, int out_size) {
    const float* features = (const float*)d_in[0];
    const void*  edge_idx = d_in[1];
    const float* W1       = (const float*)d_in[2];
    const float* b1       = (const float*)d_in[3];
    const float* W2       = (const float*)d_in[4];
    const float* b2       = (const float*)d_in[5];
    const float* b3       = (const float*)d_in[6];
    const float* b4       = (const float*)d_in[7];
    const float* head1    = (const float*)d_in[8];

    const int n = in_sizes[0] / IN_DIM;
    const int e = in_sizes[1] / 2;

    float* out = (float*)d_out;
    float* z_out  = out;
    float* h2_out = out + (size_t)n * OUT_DIM;
    float* h4_out = out + (size_t)n * OUT_DIM * 2;

    const int TPB = 256;
    dim3 blk(256);
    int aggb = ceil_div(n * 32, TPB);

    // Side stream + events (created once; work per call is identical).
    static cudaStream_t s1 = nullptr;
    static cudaEvent_t evFork = nullptr, evDone = nullptr;
    if (s1 == nullptr) {
        cudaStreamCreateWithFlags(&s1, cudaStreamNonBlocking);
        cudaEventCreateWithFlags(&evFork, cudaEventDisableTiming);
        cudaEventCreateWithFlags(&evDone, cudaEventDisableTiming);
    }

    // ---- fork: weight chain + P GEMM on s1 (independent of edges) ----
    cudaEventRecord(evFork, 0);
    cudaStreamWaitEvent(s1, evFork, 0);

    k_misc<<<6, 256, 0, s1>>>(W1, W2, b1, b3, head1);
    {
        dim3 grid(IN_DIM / 128, 2);
        k_w21<<<grid, blk, 0, s1>>>(W2, W1);
    }
    {
        dim3 grid(1, ceil_div(n, 64));   // P = X @ W21^T -> g_T
        k_mma<0, 3, 1, 0, 64><<<grid, blk, 0, s1>>>(n, OUT_DIM, IN_DIM, features,
                                                    nullptr, nullptr, nullptr);
    }
    cudaEventRecord(evDone, s1);

    // ---- main stream: CSR chain ----
    k_pre<<<ceil_div(n, TPB), TPB>>>((const int*)edge_idx, n);
    k_count<<<ceil_div(e, TPB), TPB>>>(edge_idx, e, n);
    k_scan<<<1, 1024>>>(n);            // scan + dinv + sn
    k_fill<<<ceil_div(e, TPB), TPB>>>(edge_idx, e, n);

    // ---- join ----
    cudaStreamWaitEvent(0, evDone, 0);

    // ---- S1 = Ahat P -> g_H (computes c) ; h2 = Ahat S1 + c(x)u2 + b2 ----
    k_agg<1, 2, 0, 1><<<aggb, blk>>>(nullptr, nullptr, nullptr, n);
    k_agg<2, 0, 1, 0><<<aggb, blk>>>(nullptr, h2_out, b2, n);

    // ---- z = h2 @ head1 -> z_out ----
    {
        dim3 grid(1, ceil_div(n, 64));
        k_mma<0, 5, 0, 0, 64><<<grid, blk>>>(n, OUT_DIM, OUT_DIM, h2_out,
                                             nullptr, z_out, nullptr);
    }

    // ---- S2 = Ahat z -> g_T ; Q = Ahat S2 -> g_H ----
    k_agg<0, 1, 0, 0><<<aggb, blk>>>(z_out, nullptr, nullptr, n);
    k_agg<1, 2, 0, 0><<<aggb, blk>>>(nullptr, nullptr, nullptr, n);

    // ---- h4 = Q @ W21 + c(x)u4 + b4 -> h4_out ----
    {
        dim3 grid(IN_DIM / 128, ceil_div(n, 128));
        k_mma<2, 4, 0, 1, 128><<<grid, blk>>>(n, IN_DIM, OUT_DIM, nullptr,
                                              nullptr, h4_out, b4);
    }

    (void)n_in; (void)out_size;
}

// round 12
// speedup vs baseline: 1.0151x; 1.0151x over previous
#include <cuda_runtime.h>
#include <cuda_bf16.h>
#include <cstdint>

// ---------------------------------------------------------------------------
// GAE 4-layer GCN autoencoder: algebraic fusion + CSR gather + tf32 mma GEMMs.
// This round: h4 path decoupled from z via HW21 = head1 @ W21, MLP-4 gathers,
// two-stream graph with z-GEMM fully off the critical path.
//   P  = X @ W21^T              (tf32, s1)
//   S1 = Ahat P ; h2 = Ahat S1 + c(x)u2 + b2
//   z  = h2 @ head1             (tf32, s1, parallel with aggs below)
//   R  = Ahat(Ahat h2)
//   h4 = R @ HW21 + c(x)u4 + b4 (tf32)
// ---------------------------------------------------------------------------

#define N_NODES 20000
#define IN_DIM  1024
#define HID_DIM 512
#define OUT_DIM 128
#define N_EDGES 160000

__device__ alignas(16) float g_T[(size_t)N_NODES * OUT_DIM];
__device__ alignas(16) float g_H[(size_t)N_NODES * OUT_DIM];
__device__ alignas(16) float g_W21[(size_t)OUT_DIM * IN_DIM];     // tf32-rounded [128,1024]
__device__ alignas(16) float g_HW21t[(size_t)IN_DIM * OUT_DIM];   // (head1@W21)^T tf32 [1024,128]
__device__ alignas(16) float g_Ht[(size_t)OUT_DIM * OUT_DIM];     // head1^T tf32
__device__ alignas(16) float g_u2[OUT_DIM];
__device__ alignas(16) float g_u4[IN_DIM];
__device__ float g_dinv[N_NODES];
__device__ float g_sn[N_NODES];
__device__ float g_c[N_NODES];
__device__ int   g_cnt[N_NODES];
__device__ int   g_off[N_NODES + 1];
__device__ int   g_cur[N_NODES];
__device__ int2  g_adj[N_EDGES];
__device__ int   g_is64;

// pointer selector: 0 ext, 1 g_T, 2 g_H, 3 g_W21, 4 g_HW21t, 5 g_Ht
template <int SEL>
__device__ __forceinline__ float* pick(float* ext) {
    if (SEL == 1) return g_T;
    if (SEL == 2) return g_H;
    if (SEL == 3) return g_W21;
    if (SEL == 4) return g_HW21t;
    if (SEL == 5) return g_Ht;
    return ext;
}
template <int SEL>
__device__ __forceinline__ const float* pickc(const float* ext) {
    if (SEL == 1) return g_T;
    if (SEL == 2) return g_H;
    if (SEL == 3) return g_W21;
    if (SEL == 4) return g_HW21t;
    if (SEL == 5) return g_Ht;
    return ext;
}

__device__ __forceinline__ unsigned f2t(float x) {
    unsigned u;
    asm("cvt.rna.tf32.f32 %0, %1;" : "=r"(u) : "f"(x));
    return u;
}
__device__ __forceinline__ float f2tf(float x) { return __uint_as_float(f2t(x)); }

// ---------------------------------------------------------------------------
// probe dtype + zero counters
// ---------------------------------------------------------------------------
__global__ void k_pre(const int* __restrict__ ei32, int n) {
    int i = blockIdx.x * blockDim.x + threadIdx.x;
    if (i == 0) {
        int z = (ei32[1] == 0) & (ei32[3] == 0) & (ei32[5] == 0) &
                (ei32[7] == 0) & (ei32[9] == 0) & (ei32[11] == 0);
        g_is64 = z;
    }
    if (i < n) g_cnt[i] = 0;
}

__device__ __forceinline__ int load_idx(const void* ei, int e_cnt, int row, int e) {
    if (g_is64) return (int)((const long long*)ei)[(size_t)row * e_cnt + e];
    return ((const int*)ei)[(size_t)row * e_cnt + e];
}

__global__ void k_count(const void* __restrict__ ei, int e_cnt, int n) {
    int e = blockIdx.x * blockDim.x + threadIdx.x;
    if (e < e_cnt) {
        int d = load_idx(ei, e_cnt, 1, e);
        if ((unsigned)d < (unsigned)n) atomicAdd(&g_cnt[d], 1);
    }
}

// ---------------------------------------------------------------------------
// Single-pass scan (+ dinv/sn)
// ---------------------------------------------------------------------------
#define SCAN_CHUNK ((N_NODES + 1023) / 1024)

__global__ __launch_bounds__(1024)
void k_scan(int n) {
    int tid = threadIdx.x;
    int lane = tid & 31, wid = tid >> 5;
    int base = tid * SCAN_CHUNK;
    int vloc[SCAN_CHUNK];
    int s = 0;
#pragma unroll
    for (int j = 0; j < SCAN_CHUNK; j++) {
        int i = base + j;
        int v = (i < n) ? g_cnt[i] : 0;
        vloc[j] = v;
        s += v;
    }
    int x = s;
#pragma unroll
    for (int d = 1; d < 32; d <<= 1) {
        int y = __shfl_up_sync(0xFFFFFFFFu, x, d);
        if (lane >= d) x += y;
    }
    __shared__ int ws[32];
    if (lane == 31) ws[wid] = x;
    __syncthreads();
    if (wid == 0) {
        int w = ws[lane];
#pragma unroll
        for (int d = 1; d < 32; d <<= 1) {
            int y = __shfl_up_sync(0xFFFFFFFFu, w, d);
            if (lane >= d) w += y;
        }
        ws[lane] = w;
    }
    __syncthreads();
    int excl = x - s + ((wid > 0) ? ws[wid - 1] : 0);
    if (tid == 0) g_off[0] = 0;
#pragma unroll
    for (int j = 0; j < SCAN_CHUNK; j++) {
        int i = base + j;
        if (i < n) {
            g_cur[i] = excl;
            excl += vloc[j];
            g_off[i + 1] = excl;
            float r = rsqrtf((float)(vloc[j] + 1));
            g_dinv[i] = r;
            g_sn[i] = r * r;
        }
    }
}

__global__ void k_fill(const void* __restrict__ ei, int e_cnt, int n) {
    int e = blockIdx.x * blockDim.x + threadIdx.x;
    if (e < e_cnt) {
        int s = load_idx(ei, e_cnt, 0, e);
        int d = load_idx(ei, e_cnt, 1, e);
        if ((unsigned)s >= (unsigned)n) s = 0;
        if ((unsigned)d >= (unsigned)n) d = 0;
        float w = g_dinv[s] * g_dinv[d];
        int pos = atomicAdd(&g_cur[d], 1);
        g_adj[pos] = make_int2(s, __float_as_int(w));
    }
}

// ---------------------------------------------------------------------------
// misc precomputes: u4 (blocks 0..3), u2 (block 4), head1^T tf32 (block 5)
// ---------------------------------------------------------------------------
__global__ void k_misc(const float* __restrict__ W1, const float* __restrict__ W2,
                       const float* __restrict__ b1, const float* __restrict__ b3,
                       const float* __restrict__ head1) {
    int bidx = blockIdx.x;
    if (bidx < 4) {
        int f = bidx * 256 + threadIdx.x;
        float s = 0.f;
        for (int k = 0; k < HID_DIM; k++) s += b3[k] * W1[(size_t)k * IN_DIM + f];
        g_u4[f] = s;
    } else if (bidx == 4) {
        if (threadIdx.x < OUT_DIM) {
            int o = threadIdx.x;
            float s = 0.f;
            for (int k = 0; k < HID_DIM; k++) s += W2[(size_t)o * HID_DIM + k] * b1[k];
            g_u2[o] = s;
        }
    } else {
        for (int idx = threadIdx.x; idx < OUT_DIM * OUT_DIM; idx += 256) {
            int r = idx >> 7, c = idx & 127;
            g_Ht[(size_t)c * OUT_DIM + r] = f2tf(head1[idx]);
        }
    }
}

// ---------------------------------------------------------------------------
// W21 = W2 @ W1 (fp32 FFMA, K=512) -> g_W21 tf32-rounded.
// grid (IN_DIM/128, 2), BM=64, BN=128, BK=8.
// ---------------------------------------------------------------------------
__global__ __launch_bounds__(256)
void k_w21(const float* __restrict__ A, const float* __restrict__ B) {
    __shared__ float As[8][64];
    __shared__ float Bs[8][128];
    const int bx = blockIdx.x;
    const int by = blockIdx.y;
    const int tid = threadIdx.x;
    const int tcol = tid % 16;
    const int trow = tid / 16;

    float acc[4][8];
#pragma unroll
    for (int i = 0; i < 4; i++)
#pragma unroll
        for (int j = 0; j < 8; j++) acc[i][j] = 0.0f;

    for (int k0 = 0; k0 < HID_DIM; k0 += 8) {
        if (tid < 128) {
            int aRow = tid >> 1;
            int aCol = (tid & 1) << 2;
            int m = by * 64 + aRow;
            float4 av = *(const float4*)(A + (size_t)m * HID_DIM + k0 + aCol);
            As[aCol + 0][aRow] = av.x;
            As[aCol + 1][aRow] = av.y;
            As[aCol + 2][aRow] = av.z;
            As[aCol + 3][aRow] = av.w;
        }
        {
            int kk = tid >> 5;
            int nn = (tid & 31) << 2;
            float4 bv = *(const float4*)(B + (size_t)(k0 + kk) * IN_DIM + bx * 128 + nn);
            *(float4*)&Bs[kk][nn] = bv;
        }
        __syncthreads();
#pragma unroll
        for (int k = 0; k < 8; k++) {
            float ra[4], rb[8];
#pragma unroll
            for (int i = 0; i < 4; i++) ra[i] = As[k][trow * 4 + i];
#pragma unroll
            for (int j = 0; j < 8; j++) rb[j] = Bs[k][tcol * 8 + j];
#pragma unroll
            for (int i = 0; i < 4; i++)
#pragma unroll
                for (int j = 0; j < 8; j++) acc[i][j] += ra[i] * rb[j];
        }
        __syncthreads();
    }
#pragma unroll
    for (int i = 0; i < 4; i++) {
        int m = by * 64 + trow * 4 + i;
#pragma unroll
        for (int j = 0; j < 8; j++) {
            int col = bx * 128 + tcol * 8 + j;
            g_W21[(size_t)m * IN_DIM + col] = f2tf(acc[i][j]);
        }
    }
}

// ---------------------------------------------------------------------------
// HW21^T: HW21 = head1 @ W21  [128,1024] (fp32 FFMA over K=128),
// stored transposed tf32 into g_HW21t [1024,128].
// grid (IN_DIM/128, 2), BM=64, BN=128, BK=8.
// ---------------------------------------------------------------------------
__global__ __launch_bounds__(256)
void k_hw21(const float* __restrict__ head1) {
    __shared__ float As[8][64];
    __shared__ float Bs[8][128];
    const int bx = blockIdx.x;
    const int by = blockIdx.y;
    const int tid = threadIdx.x;
    const int tcol = tid % 16;
    const int trow = tid / 16;

    float acc[4][8];
#pragma unroll
    for (int i = 0; i < 4; i++)
#pragma unroll
        for (int j = 0; j < 8; j++) acc[i][j] = 0.0f;

    for (int k0 = 0; k0 < OUT_DIM; k0 += 8) {
        if (tid < 128) {
            int aRow = tid >> 1;
            int aCol = (tid & 1) << 2;
            int m = by * 64 + aRow;
            float4 av = *(const float4*)(head1 + (size_t)m * OUT_DIM + k0 + aCol);
            As[aCol + 0][aRow] = av.x;
            As[aCol + 1][aRow] = av.y;
            As[aCol + 2][aRow] = av.z;
            As[aCol + 3][aRow] = av.w;
        }
        {
            int kk = tid >> 5;
            int nn = (tid & 31) << 2;
            float4 bv = *(const float4*)(g_W21 + (size_t)(k0 + kk) * IN_DIM + bx * 128 + nn);
            *(float4*)&Bs[kk][nn] = bv;
        }
        __syncthreads();
#pragma unroll
        for (int k = 0; k < 8; k++) {
            float ra[4], rb[8];
#pragma unroll
            for (int i = 0; i < 4; i++) ra[i] = As[k][trow * 4 + i];
#pragma unroll
            for (int j = 0; j < 8; j++) rb[j] = Bs[k][tcol * 8 + j];
#pragma unroll
            for (int i = 0; i < 4; i++)
#pragma unroll
                for (int j = 0; j < 8; j++) acc[i][j] += ra[i] * rb[j];
        }
        __syncthreads();
    }
#pragma unroll
    for (int i = 0; i < 4; i++) {
        int m = by * 64 + trow * 4 + i;   // row of HW21 (0..127)
#pragma unroll
        for (int j = 0; j < 8; j++) {
            int col = bx * 128 + tcol * 8 + j;  // col of HW21 (0..1023)
            g_HW21t[(size_t)col * OUT_DIM + m] = f2tf(acc[i][j]);
        }
    }
}

// ---------------------------------------------------------------------------
// tf32 tensor-core GEMM (TN form), register-prefetch pipelined.
// ---------------------------------------------------------------------------
template <int ASEL, int BSEL, int CSEL, int CORR4, int BMv>
__global__ __launch_bounds__(256)
void k_mma(int M, int Nn, int K,
           const float* __restrict__ Aext,
           const float* __restrict__ Bext,
           float* __restrict__ Cext,
           const float* __restrict__ bias) {
    constexpr int MT  = BMv / 32;
    constexpr int AR4 = (BMv * 32) / (256 * 4);
    const float* A = pickc<ASEL>(Aext);
    const float* B = pickc<BSEL>(Bext);
    float*       C = pick<CSEL>(Cext);

    __shared__ float As[BMv][36];
    __shared__ float Bs[128][36];

    const int tid  = threadIdx.x;
    const int lane = tid & 31;
    const int wid  = tid >> 5;
    const int g    = lane >> 2;
    const int t    = lane & 3;
    const int wm   = (wid & 1) * (BMv / 2);
    const int wn   = (wid >> 1) * 32;
    const int bx   = blockIdx.x;
    const int by   = blockIdx.y;

    float4 ar[AR4], br[4];

    auto loadA = [&](int k0) {
#pragma unroll
        for (int i = 0; i < AR4; i++) {
            int f4 = tid + i * 256;
            int m  = f4 >> 3;
            int kq = (f4 & 7) << 2;
            int gm = by * BMv + m;
            ar[i] = (gm < M) ? *(const float4*)(A + (size_t)gm * K + k0 + kq)
                             : make_float4(0.f, 0.f, 0.f, 0.f);
        }
    };
    auto loadB = [&](int k0) {
#pragma unroll
        for (int i = 0; i < 4; i++) {
            int f4 = tid + i * 256;
            int nn = f4 >> 3;
            int kq = (f4 & 7) << 2;
            br[i] = *(const float4*)(B + (size_t)(bx * 128 + nn) * K + k0 + kq);
        }
    };
    auto storeA = [&]() {
#pragma unroll
        for (int i = 0; i < AR4; i++) {
            int f4 = tid + i * 256;
            int m  = f4 >> 3;
            int kq = (f4 & 7) << 2;
            float4 w;
            w.x = f2tf(ar[i].x); w.y = f2tf(ar[i].y);
            w.z = f2tf(ar[i].z); w.w = f2tf(ar[i].w);
            *(float4*)&As[m][kq] = w;
        }
    };
    auto storeB = [&]() {
#pragma unroll
        for (int i = 0; i < 4; i++) {
            int f4 = tid + i * 256;
            int nn = f4 >> 3;
            int kq = (f4 & 7) << 2;
            *(float4*)&Bs[nn][kq] = br[i];
        }
    };

    float c[MT][4][4];
#pragma unroll
    for (int i = 0; i < MT; i++)
#pragma unroll
        for (int j = 0; j < 4; j++)
#pragma unroll
            for (int r = 0; r < 4; r++) c[i][j][r] = 0.0f;

    const int nt = K / 32;
    loadA(0); loadB(0);
    storeA(); storeB();
    __syncthreads();

    for (int it = 0; it < nt; it++) {
        if (it + 1 < nt) { loadA((it + 1) * 32); loadB((it + 1) * 32); }

#pragma unroll
        for (int ks = 0; ks < 4; ks++) {
            unsigned a[MT][4], b[4][2];
            int kk = ks * 8 + t;
#pragma unroll
            for (int i = 0; i < MT; i++) {
                int mr = wm + i * 16 + g;
                a[i][0] = __float_as_uint(As[mr    ][kk    ]);
                a[i][1] = __float_as_uint(As[mr + 8][kk    ]);
                a[i][2] = __float_as_uint(As[mr    ][kk + 4]);
                a[i][3] = __float_as_uint(As[mr + 8][kk + 4]);
            }
#pragma unroll
            for (int j = 0; j < 4; j++) {
                int nr = wn + j * 8 + g;
                b[j][0] = __float_as_uint(Bs[nr][kk    ]);
                b[j][1] = __float_as_uint(Bs[nr][kk + 4]);
            }
#pragma unroll
            for (int i = 0; i < MT; i++)
#pragma unroll
                for (int j = 0; j < 4; j++) {
                    asm volatile(
                        "mma.sync.aligned.m16n8k8.row.col.f32.tf32.tf32.f32 "
                        "{%0,%1,%2,%3}, {%4,%5,%6,%7}, {%8,%9}, {%0,%1,%2,%3};"
                        : "+f"(c[i][j][0]), "+f"(c[i][j][1]),
                          "+f"(c[i][j][2]), "+f"(c[i][j][3])
                        : "r"(a[i][0]), "r"(a[i][1]), "r"(a[i][2]), "r"(a[i][3]),
                          "r"(b[j][0]), "r"(b[j][1]));
                }
        }
        __syncthreads();
        if (it + 1 < nt) {
            storeA(); storeB();
            __syncthreads();
        }
    }

#pragma unroll
    for (int j = 0; j < 4; j++) {
        int cn = bx * 128 + wn + j * 8 + t * 2;
        float e0 = bias ? bias[cn]     : 0.0f;
        float e1 = bias ? bias[cn + 1] : 0.0f;
        float u40 = CORR4 ? g_u4[cn]     : 0.0f;
        float u41 = CORR4 ? g_u4[cn + 1] : 0.0f;
#pragma unroll
        for (int i = 0; i < MT; i++) {
            int r0 = by * BMv + wm + i * 16 + g;
            if (r0 < M) {
                float a0 = c[i][j][0] + e0, a1 = c[i][j][1] + e1;
                if (CORR4) { float ci = g_c[r0]; a0 += ci * u40; a1 += ci * u41; }
                *(float2*)(C + (size_t)r0 * Nn + cn) = make_float2(a0, a1);
            }
            int r1 = r0 + 8;
            if (r1 < M) {
                float a2 = c[i][j][2] + e0, a3 = c[i][j][3] + e1;
                if (CORR4) { float ci = g_c[r1]; a2 += ci * u40; a3 += ci * u41; }
                *(float2*)(C + (size_t)r1 * Nn + cn) = make_float2(a2, a3);
            }
        }
    }
}

// ---------------------------------------------------------------------------
// Aggregation (warp-per-node CSR gather), MLP-4 unrolled edge loop.
// ---------------------------------------------------------------------------
template <int SSEL, int DSEL, int CORR, int WRC>
__global__ __launch_bounds__(256)
void k_agg(const float* __restrict__ Sext,
           float* __restrict__ Dext,
           const float* __restrict__ b,
           int n) {
    int gw = (blockIdx.x * 256 + threadIdx.x) >> 5;
    if (gw >= n) return;
    int lane = threadIdx.x & 31;
    const float* S = pickc<SSEL>(Sext);
    float*       D = pick<DSEL>(Dext);

    int beg = g_off[gw];
    int end = g_off[gw + 1];
    float sn = g_sn[gw];
    float4 v = *(const float4*)(S + (size_t)gw * OUT_DIM + lane * 4);
    float4 acc = make_float4(sn * v.x, sn * v.y, sn * v.z, sn * v.w);
    float cacc = sn;

    int p = beg;
    for (; p + 4 <= end; p += 4) {
        int2 e0 = g_adj[p], e1 = g_adj[p + 1], e2 = g_adj[p + 2], e3 = g_adj[p + 3];
        float w0 = __int_as_float(e0.y), w1 = __int_as_float(e1.y);
        float w2 = __int_as_float(e2.y), w3 = __int_as_float(e3.y);
        float4 u0 = *(const float4*)(S + (size_t)e0.x * OUT_DIM + lane * 4);
        float4 u1 = *(const float4*)(S + (size_t)e1.x * OUT_DIM + lane * 4);
        float4 u2 = *(const float4*)(S + (size_t)e2.x * OUT_DIM + lane * 4);
        float4 u3 = *(const float4*)(S + (size_t)e3.x * OUT_DIM + lane * 4);
        if (WRC) cacc += w0 + w1 + w2 + w3;
        acc.x += w0 * u0.x; acc.y += w0 * u0.y; acc.z += w0 * u0.z; acc.w += w0 * u0.w;
        acc.x += w1 * u1.x; acc.y += w1 * u1.y; acc.z += w1 * u1.z; acc.w += w1 * u1.w;
        acc.x += w2 * u2.x; acc.y += w2 * u2.y; acc.z += w2 * u2.z; acc.w += w2 * u2.w;
        acc.x += w3 * u3.x; acc.y += w3 * u3.y; acc.z += w3 * u3.z; acc.w += w3 * u3.w;
    }
    for (; p < end; p++) {
        int2 pr = g_adj[p];
        float w = __int_as_float(pr.y);
        if (WRC) cacc += w;
        float4 u = *(const float4*)(S + (size_t)pr.x * OUT_DIM + lane * 4);
        acc.x += w * u.x; acc.y += w * u.y; acc.z += w * u.z; acc.w += w * u.w;
    }

    if (WRC && lane == 0) g_c[gw] = cacc;

    if (CORR) {
        float ci = g_c[gw];
        int f = lane * 4;
        acc.x += ci * g_u2[f + 0] + b[f + 0];
        acc.y += ci * g_u2[f + 1] + b[f + 1];
        acc.z += ci * g_u2[f + 2] + b[f + 2];
        acc.w += ci * g_u2[f + 3] + b[f + 3];
    }
    *(float4*)(D + (size_t)gw * OUT_DIM + lane * 4) = acc;
}

// ---------------------------------------------------------------------------
static inline int ceil_div(int a, int b) { return (a + b - 1) / b; }

extern "C" void kernel_launch(void* const* d_in, const int* in_sizes, int n_in,
                              void* d_out, int out_size) {
    const float* features = (const float*)d_in[0];
    const void*  edge_idx = d_in[1];
    const float* W1       = (const float*)d_in[2];
    const float* b1       = (const float*)d_in[3];
    const float* W2       = (const float*)d_in[4];
    const float* b2       = (const float*)d_in[5];
    const float* b3       = (const float*)d_in[6];
    const float* b4       = (const float*)d_in[7];
    const float* head1    = (const float*)d_in[8];

    const int n = in_sizes[0] / IN_DIM;
    const int e = in_sizes[1] / 2;

    float* out = (float*)d_out;
    float* z_out  = out;
    float* h2_out = out + (size_t)n * OUT_DIM;
    float* h4_out = out + (size_t)n * OUT_DIM * 2;

    const int TPB = 256;
    dim3 blk(256);
    int aggb = ceil_div(n * 32, TPB);

    static cudaStream_t s1 = nullptr;
    static cudaEvent_t evFork = nullptr, evP = nullptr, evHW = nullptr,
                       evH2 = nullptr, evZ = nullptr;
    if (s1 == nullptr) {
        cudaStreamCreateWithFlags(&s1, cudaStreamNonBlocking);
        cudaEventCreateWithFlags(&evFork, cudaEventDisableTiming);
        cudaEventCreateWithFlags(&evP,    cudaEventDisableTiming);
        cudaEventCreateWithFlags(&evHW,   cudaEventDisableTiming);
        cudaEventCreateWithFlags(&evH2,   cudaEventDisableTiming);
        cudaEventCreateWithFlags(&evZ,    cudaEventDisableTiming);
    }

    // ---- fork ----
    cudaEventRecord(evFork, 0);
    cudaStreamWaitEvent(s1, evFork, 0);

    // s1: weights -> P -> HW21; later z (after h2).
    k_misc<<<6, 256, 0, s1>>>(W1, W2, b1, b3, head1);
    {
        dim3 grid(IN_DIM / 128, 2);
        k_w21<<<grid, blk, 0, s1>>>(W2, W1);
    }
    {
        dim3 grid(1, ceil_div(n, 64));   // P = X @ W21^T -> g_T
        k_mma<0, 3, 1, 0, 64><<<grid, blk, 0, s1>>>(n, OUT_DIM, IN_DIM, features,
                                                    nullptr, nullptr, nullptr);
    }
    cudaEventRecord(evP, s1);
    {
        dim3 grid(IN_DIM / 128, 2);      // HW21t
        k_hw21<<<grid, blk, 0, s1>>>(head1);
    }
    cudaEventRecord(evHW, s1);

    // s0: CSR chain
    k_pre<<<ceil_div(n, TPB), TPB>>>((const int*)edge_idx, n);
    k_count<<<ceil_div(e, TPB), TPB>>>(edge_idx, e, n);
    k_scan<<<1, 1024>>>(n);
    k_fill<<<ceil_div(e, TPB), TPB>>>(edge_idx, e, n);

    // join for P
    cudaStreamWaitEvent(0, evP, 0);

    // ---- S1 = Ahat P -> g_H (computes c) ; h2 = Ahat S1 + c(x)u2 + b2 ----
    k_agg<1, 2, 0, 1><<<aggb, blk>>>(nullptr, nullptr, nullptr, n);
    k_agg<2, 0, 1, 0><<<aggb, blk>>>(nullptr, h2_out, b2, n);
    cudaEventRecord(evH2, 0);

    // s1: z = h2 @ head1 (parallel with agg3/agg4/h4 below)
    cudaStreamWaitEvent(s1, evH2, 0);
    {
        dim3 grid(1, ceil_div(n, 64));
        k_mma<0, 5, 0, 0, 64><<<grid, blk, 0, s1>>>(n, OUT_DIM, OUT_DIM, h2_out,
                                                    nullptr, z_out, nullptr);
    }
    cudaEventRecord(evZ, s1);

    // ---- S2 = Ahat h2 -> g_T ; R = Ahat S2 -> g_H ----
    k_agg<0, 1, 0, 0><<<aggb, blk>>>(h2_out, nullptr, nullptr, n);
    k_agg<1, 2, 0, 0><<<aggb, blk>>>(nullptr, nullptr, nullptr, n);

    // ---- h4 = R @ HW21 + c(x)u4 + b4 ----
    cudaStreamWaitEvent(0, evHW, 0);
    {
        dim3 grid(IN_DIM / 128, ceil_div(n, 128));
        k_mma<2, 4, 0, 1, 128><<<grid, blk>>>(n, IN_DIM, OUT_DIM, nullptr,
                                              nullptr, h4_out, b4);
    }

    // join z before capture end
    cudaStreamWaitEvent(0, evZ, 0);

    (void)n_in; (void)out_size;
}

// round 13
// speedup vs baseline: 1.0965x; 1.0803x over previous
#include <cuda_runtime.h>
#include <cuda_fp16.h>
#include <cstdint>

// ---------------------------------------------------------------------------
// GAE 4-layer GCN autoencoder: algebraic fusion + CSR gather + fp16 mma GEMMs
// (fp16 mantissa == tf32 mantissa; 2x mma.sync throughput, half smem traffic,
//  contiguous half2 fragment loads).
//   P  = X @ W21^T              (fp16 mma, s1)
//   S1 = Ahat P ; h2 = Ahat S1 + c(x)u2 + b2   (exact fp32 gathers)
//   z  = h2 @ head1             (fp16 mma, s1, off critical path)
//   R  = Ahat(Ahat h2)
//   h4 = R @ (head1@W21) + c(x)u4 + b4          (fp16 mma)
// ---------------------------------------------------------------------------

#define N_NODES 20000
#define IN_DIM  1024
#define HID_DIM 512
#define OUT_DIM 128
#define N_EDGES 160000

__device__ alignas(16) float  g_T[(size_t)N_NODES * OUT_DIM];
__device__ alignas(16) float  g_H[(size_t)N_NODES * OUT_DIM];
__device__ alignas(16) float  g_W21[(size_t)OUT_DIM * IN_DIM];      // fp32 (for hw21)
__device__ alignas(16) __half g_W21h[(size_t)OUT_DIM * IN_DIM];     // [128,1024] n-major
__device__ alignas(16) __half g_HW21th[(size_t)IN_DIM * OUT_DIM];   // [1024,128] n-major
__device__ alignas(16) __half g_Hth[(size_t)OUT_DIM * OUT_DIM];     // head1^T [128,128]
__device__ alignas(16) float  g_u2[OUT_DIM];
__device__ alignas(16) float  g_u4[IN_DIM];
__device__ float g_dinv[N_NODES];
__device__ float g_sn[N_NODES];
__device__ float g_c[N_NODES];
__device__ int   g_cnt[N_NODES];
__device__ int   g_off[N_NODES + 1];
__device__ int   g_cur[N_NODES];
__device__ int2  g_adj[N_EDGES];
__device__ int   g_is64;

// float selector: 0 ext, 1 g_T, 2 g_H
template <int SEL>
__device__ __forceinline__ float* pick(float* ext) {
    if (SEL == 1) return g_T;
    if (SEL == 2) return g_H;
    return ext;
}
template <int SEL>
__device__ __forceinline__ const float* pickc(const float* ext) {
    if (SEL == 1) return g_T;
    if (SEL == 2) return g_H;
    return ext;
}
// half B selector: 3 g_W21h, 4 g_HW21th, 5 g_Hth
template <int SEL>
__device__ __forceinline__ const __half* pickh() {
    if (SEL == 3) return g_W21h;
    if (SEL == 4) return g_HW21th;
    return g_Hth;
}

// ---------------------------------------------------------------------------
// probe dtype + zero counters
// ---------------------------------------------------------------------------
__global__ void k_pre(const int* __restrict__ ei32, int n) {
    int i = blockIdx.x * blockDim.x + threadIdx.x;
    if (i == 0) {
        int z = (ei32[1] == 0) & (ei32[3] == 0) & (ei32[5] == 0) &
                (ei32[7] == 0) & (ei32[9] == 0) & (ei32[11] == 0);
        g_is64 = z;
    }
    if (i < n) g_cnt[i] = 0;
}

__device__ __forceinline__ int load_idx(const void* ei, int e_cnt, int row, int e) {
    if (g_is64) return (int)((const long long*)ei)[(size_t)row * e_cnt + e];
    return ((const int*)ei)[(size_t)row * e_cnt + e];
}

__global__ void k_count(const void* __restrict__ ei, int e_cnt, int n) {
    int e = blockIdx.x * blockDim.x + threadIdx.x;
    if (e < e_cnt) {
        int d = load_idx(ei, e_cnt, 1, e);
        if ((unsigned)d < (unsigned)n) atomicAdd(&g_cnt[d], 1);
    }
}

// ---------------------------------------------------------------------------
// Single-pass scan (+ dinv/sn)
// ---------------------------------------------------------------------------
#define SCAN_CHUNK ((N_NODES + 1023) / 1024)

__global__ __launch_bounds__(1024)
void k_scan(int n) {
    int tid = threadIdx.x;
    int lane = tid & 31, wid = tid >> 5;
    int base = tid * SCAN_CHUNK;
    int vloc[SCAN_CHUNK];
    int s = 0;
#pragma unroll
    for (int j = 0; j < SCAN_CHUNK; j++) {
        int i = base + j;
        int v = (i < n) ? g_cnt[i] : 0;
        vloc[j] = v;
        s += v;
    }
    int x = s;
#pragma unroll
    for (int d = 1; d < 32; d <<= 1) {
        int y = __shfl_up_sync(0xFFFFFFFFu, x, d);
        if (lane >= d) x += y;
    }
    __shared__ int ws[32];
    if (lane == 31) ws[wid] = x;
    __syncthreads();
    if (wid == 0) {
        int w = ws[lane];
#pragma unroll
        for (int d = 1; d < 32; d <<= 1) {
            int y = __shfl_up_sync(0xFFFFFFFFu, w, d);
            if (lane >= d) w += y;
        }
        ws[lane] = w;
    }
    __syncthreads();
    int excl = x - s + ((wid > 0) ? ws[wid - 1] : 0);
    if (tid == 0) g_off[0] = 0;
#pragma unroll
    for (int j = 0; j < SCAN_CHUNK; j++) {
        int i = base + j;
        if (i < n) {
            g_cur[i] = excl;
            excl += vloc[j];
            g_off[i + 1] = excl;
            float r = rsqrtf((float)(vloc[j] + 1));
            g_dinv[i] = r;
            g_sn[i] = r * r;
        }
    }
}

__global__ void k_fill(const void* __restrict__ ei, int e_cnt, int n) {
    int e = blockIdx.x * blockDim.x + threadIdx.x;
    if (e < e_cnt) {
        int s = load_idx(ei, e_cnt, 0, e);
        int d = load_idx(ei, e_cnt, 1, e);
        if ((unsigned)s >= (unsigned)n) s = 0;
        if ((unsigned)d >= (unsigned)n) d = 0;
        float w = g_dinv[s] * g_dinv[d];
        int pos = atomicAdd(&g_cur[d], 1);
        g_adj[pos] = make_int2(s, __float_as_int(w));
    }
}

// ---------------------------------------------------------------------------
// misc precomputes: u4 (blocks 0..3), u2 (block 4), head1^T half (block 5)
// ---------------------------------------------------------------------------
__global__ void k_misc(const float* __restrict__ W1, const float* __restrict__ W2,
                       const float* __restrict__ b1, const float* __restrict__ b3,
                       const float* __restrict__ head1) {
    int bidx = blockIdx.x;
    if (bidx < 4) {
        int f = bidx * 256 + threadIdx.x;
        float s = 0.f;
        for (int k = 0; k < HID_DIM; k++) s += b3[k] * W1[(size_t)k * IN_DIM + f];
        g_u4[f] = s;
    } else if (bidx == 4) {
        if (threadIdx.x < OUT_DIM) {
            int o = threadIdx.x;
            float s = 0.f;
            for (int k = 0; k < HID_DIM; k++) s += W2[(size_t)o * HID_DIM + k] * b1[k];
            g_u2[o] = s;
        }
    } else {
        for (int idx = threadIdx.x; idx < OUT_DIM * OUT_DIM; idx += 256) {
            int r = idx >> 7, c = idx & 127;
            g_Hth[(size_t)c * OUT_DIM + r] = __float2half(head1[idx]);
        }
    }
}

// ---------------------------------------------------------------------------
// W21 = W2 @ W1 (fp32 FFMA, K=512) -> g_W21 fp32 + g_W21h half.
// grid (IN_DIM/128, 2), BM=64, BN=128, BK=8.
// ---------------------------------------------------------------------------
__global__ __launch_bounds__(256)
void k_w21(const float* __restrict__ A, const float* __restrict__ B) {
    __shared__ float As[8][64];
    __shared__ float Bs[8][128];
    const int bx = blockIdx.x;
    const int by = blockIdx.y;
    const int tid = threadIdx.x;
    const int tcol = tid % 16;
    const int trow = tid / 16;

    float acc[4][8];
#pragma unroll
    for (int i = 0; i < 4; i++)
#pragma unroll
        for (int j = 0; j < 8; j++) acc[i][j] = 0.0f;

    for (int k0 = 0; k0 < HID_DIM; k0 += 8) {
        if (tid < 128) {
            int aRow = tid >> 1;
            int aCol = (tid & 1) << 2;
            int m = by * 64 + aRow;
            float4 av = *(const float4*)(A + (size_t)m * HID_DIM + k0 + aCol);
            As[aCol + 0][aRow] = av.x;
            As[aCol + 1][aRow] = av.y;
            As[aCol + 2][aRow] = av.z;
            As[aCol + 3][aRow] = av.w;
        }
        {
            int kk = tid >> 5;
            int nn = (tid & 31) << 2;
            float4 bv = *(const float4*)(B + (size_t)(k0 + kk) * IN_DIM + bx * 128 + nn);
            *(float4*)&Bs[kk][nn] = bv;
        }
        __syncthreads();
#pragma unroll
        for (int k = 0; k < 8; k++) {
            float ra[4], rb[8];
#pragma unroll
            for (int i = 0; i < 4; i++) ra[i] = As[k][trow * 4 + i];
#pragma unroll
            for (int j = 0; j < 8; j++) rb[j] = Bs[k][tcol * 8 + j];
#pragma unroll
            for (int i = 0; i < 4; i++)
#pragma unroll
                for (int j = 0; j < 8; j++) acc[i][j] += ra[i] * rb[j];
        }
        __syncthreads();
    }
#pragma unroll
    for (int i = 0; i < 4; i++) {
        int m = by * 64 + trow * 4 + i;
#pragma unroll
        for (int j = 0; j < 8; j++) {
            int col = bx * 128 + tcol * 8 + j;
            g_W21[(size_t)m * IN_DIM + col]  = acc[i][j];
            g_W21h[(size_t)m * IN_DIM + col] = __float2half(acc[i][j]);
        }
    }
}

// ---------------------------------------------------------------------------
// HW21 = head1 @ W21 [128,1024] (fp32 FFMA, K=128) -> g_HW21th half transposed.
// grid (IN_DIM/128, 2).
// ---------------------------------------------------------------------------
__global__ __launch_bounds__(256)
void k_hw21(const float* __restrict__ head1) {
    __shared__ float As[8][64];
    __shared__ float Bs[8][128];
    const int bx = blockIdx.x;
    const int by = blockIdx.y;
    const int tid = threadIdx.x;
    const int tcol = tid % 16;
    const int trow = tid / 16;

    float acc[4][8];
#pragma unroll
    for (int i = 0; i < 4; i++)
#pragma unroll
        for (int j = 0; j < 8; j++) acc[i][j] = 0.0f;

    for (int k0 = 0; k0 < OUT_DIM; k0 += 8) {
        if (tid < 128) {
            int aRow = tid >> 1;
            int aCol = (tid & 1) << 2;
            int m = by * 64 + aRow;
            float4 av = *(const float4*)(head1 + (size_t)m * OUT_DIM + k0 + aCol);
            As[aCol + 0][aRow] = av.x;
            As[aCol + 1][aRow] = av.y;
            As[aCol + 2][aRow] = av.z;
            As[aCol + 3][aRow] = av.w;
        }
        {
            int kk = tid >> 5;
            int nn = (tid & 31) << 2;
            float4 bv = *(const float4*)(g_W21 + (size_t)(k0 + kk) * IN_DIM + bx * 128 + nn);
            *(float4*)&Bs[kk][nn] = bv;
        }
        __syncthreads();
#pragma unroll
        for (int k = 0; k < 8; k++) {
            float ra[4], rb[8];
#pragma unroll
            for (int i = 0; i < 4; i++) ra[i] = As[k][trow * 4 + i];
#pragma unroll
            for (int j = 0; j < 8; j++) rb[j] = Bs[k][tcol * 8 + j];
#pragma unroll
            for (int i = 0; i < 4; i++)
#pragma unroll
                for (int j = 0; j < 8; j++) acc[i][j] += ra[i] * rb[j];
        }
        __syncthreads();
    }
#pragma unroll
    for (int i = 0; i < 4; i++) {
        int m = by * 64 + trow * 4 + i;
#pragma unroll
        for (int j = 0; j < 8; j++) {
            int col = bx * 128 + tcol * 8 + j;
            g_HW21th[(size_t)col * OUT_DIM + m] = __float2half(acc[i][j]);
        }
    }
}

// ---------------------------------------------------------------------------
// fp16 tensor-core GEMM (TN form), m16n8k16, register-prefetch pipelined.
//   C[M,Nn] = A[M,K](fp32, cvt to fp16) @ B'[K,Nn] (B stored [Nn,K] half)
//   + bias[n] + CORR4 (c[m]*u4[n]). BMv in {64,128}, BN=128, BK=32, 8 warps.
// Smem row stride 40 halfs -> conflict-free fragment LDS.
// ---------------------------------------------------------------------------
template <int ASEL, int BSEL, int CSEL, int CORR4, int BMv>
__global__ __launch_bounds__(256)
void k_mma(int M, int Nn, int K,
           const float* __restrict__ Aext,
           float* __restrict__ Cext,
           const float* __restrict__ bias) {
    constexpr int MT  = BMv / 32;               // m16-tiles per warp
    constexpr int AR4 = BMv / 32;               // float4 per thread for A tile
    const float*  A = pickc<ASEL>(Aext);
    const __half* B = pickh<BSEL>();
    float*        C = pick<CSEL>(Cext);

    __shared__ __half As[BMv][40];
    __shared__ __half Bs[128][40];

    const int tid  = threadIdx.x;
    const int lane = tid & 31;
    const int wid  = tid >> 5;
    const int g    = lane >> 2;
    const int t    = lane & 3;
    const int wm   = (wid & 1) * (BMv / 2);
    const int wn   = (wid >> 1) * 32;
    const int bx   = blockIdx.x;
    const int by   = blockIdx.y;

    float4 ar[AR4];
    uint4  br4[2];

    auto loadA = [&](int k0) {
#pragma unroll
        for (int i = 0; i < AR4; i++) {
            int f4 = tid + i * 256;
            int m  = f4 >> 3;
            int kq = (f4 & 7) << 2;
            int gm = by * BMv + m;
            ar[i] = (gm < M) ? *(const float4*)(A + (size_t)gm * K + k0 + kq)
                             : make_float4(0.f, 0.f, 0.f, 0.f);
        }
    };
    auto loadB = [&](int k0) {
#pragma unroll
        for (int i = 0; i < 2; i++) {
            int f4 = tid + i * 256;
            int nn = f4 >> 2;
            int kq = (f4 & 3) << 3;
            br4[i] = *(const uint4*)(B + (size_t)(bx * 128 + nn) * K + k0 + kq);
        }
    };
    auto storeA = [&]() {
#pragma unroll
        for (int i = 0; i < AR4; i++) {
            int f4 = tid + i * 256;
            int m  = f4 >> 3;
            int kq = (f4 & 7) << 2;
            __half2 h01 = __floats2half2_rn(ar[i].x, ar[i].y);
            __half2 h23 = __floats2half2_rn(ar[i].z, ar[i].w);
            *(__half2*)&As[m][kq]     = h01;
            *(__half2*)&As[m][kq + 2] = h23;
        }
    };
    auto storeB = [&]() {
#pragma unroll
        for (int i = 0; i < 2; i++) {
            int f4 = tid + i * 256;
            int nn = f4 >> 2;
            int kq = (f4 & 3) << 3;
            *(uint4*)&Bs[nn][kq] = br4[i];
        }
    };

    float c[MT][4][4];
#pragma unroll
    for (int i = 0; i < MT; i++)
#pragma unroll
        for (int j = 0; j < 4; j++)
#pragma unroll
            for (int r = 0; r < 4; r++) c[i][j][r] = 0.0f;

    const int nt = K / 32;
    loadA(0); loadB(0);
    storeA(); storeB();
    __syncthreads();

    for (int it = 0; it < nt; it++) {
        if (it + 1 < nt) { loadA((it + 1) * 32); loadB((it + 1) * 32); }

#pragma unroll
        for (int ks = 0; ks < 2; ks++) {
            unsigned a[MT][4], b[4][2];
            int kb = ks * 16 + 2 * t;
#pragma unroll
            for (int i = 0; i < MT; i++) {
                int mr = wm + i * 16 + g;
                a[i][0] = *(const unsigned*)&As[mr    ][kb    ];
                a[i][1] = *(const unsigned*)&As[mr + 8][kb    ];
                a[i][2] = *(const unsigned*)&As[mr    ][kb + 8];
                a[i][3] = *(const unsigned*)&As[mr + 8][kb + 8];
            }
#pragma unroll
            for (int j = 0; j < 4; j++) {
                int nr = wn + j * 8 + g;
                b[j][0] = *(const unsigned*)&Bs[nr][kb    ];
                b[j][1] = *(const unsigned*)&Bs[nr][kb + 8];
            }
#pragma unroll
            for (int i = 0; i < MT; i++)
#pragma unroll
                for (int j = 0; j < 4; j++) {
                    asm volatile(
                        "mma.sync.aligned.m16n8k16.row.col.f32.f16.f16.f32 "
                        "{%0,%1,%2,%3}, {%4,%5,%6,%7}, {%8,%9}, {%0,%1,%2,%3};"
                        : "+f"(c[i][j][0]), "+f"(c[i][j][1]),
                          "+f"(c[i][j][2]), "+f"(c[i][j][3])
                        : "r"(a[i][0]), "r"(a[i][1]), "r"(a[i][2]), "r"(a[i][3]),
                          "r"(b[j][0]), "r"(b[j][1]));
                }
        }
        __syncthreads();
        if (it + 1 < nt) {
            storeA(); storeB();
            __syncthreads();
        }
    }

#pragma unroll
    for (int j = 0; j < 4; j++) {
        int cn = bx * 128 + wn + j * 8 + t * 2;
        float e0 = bias ? bias[cn]     : 0.0f;
        float e1 = bias ? bias[cn + 1] : 0.0f;
        float u40 = CORR4 ? g_u4[cn]     : 0.0f;
        float u41 = CORR4 ? g_u4[cn + 1] : 0.0f;
#pragma unroll
        for (int i = 0; i < MT; i++) {
            int r0 = by * BMv + wm + i * 16 + g;
            if (r0 < M) {
                float a0 = c[i][j][0] + e0, a1 = c[i][j][1] + e1;
                if (CORR4) { float ci = g_c[r0]; a0 += ci * u40; a1 += ci * u41; }
                *(float2*)(C + (size_t)r0 * Nn + cn) = make_float2(a0, a1);
            }
            int r1 = r0 + 8;
            if (r1 < M) {
                float a2 = c[i][j][2] + e0, a3 = c[i][j][3] + e1;
                if (CORR4) { float ci = g_c[r1]; a2 += ci * u40; a3 += ci * u41; }
                *(float2*)(C + (size_t)r1 * Nn + cn) = make_float2(a2, a3);
            }
        }
    }
}

// ---------------------------------------------------------------------------
// Aggregation (warp-per-node CSR gather), MLP-4 unrolled, exact fp32.
// ---------------------------------------------------------------------------
template <int SSEL, int DSEL, int CORR, int WRC>
__global__ __launch_bounds__(256)
void k_agg(const float* __restrict__ Sext,
           float* __restrict__ Dext,
           const float* __restrict__ b,
           int n) {
    int gw = (blockIdx.x * 256 + threadIdx.x) >> 5;
    if (gw >= n) return;
    int lane = threadIdx.x & 31;
    const float* S = pickc<SSEL>(Sext);
    float*       D = pick<DSEL>(Dext);

    int beg = g_off[gw];
    int end = g_off[gw + 1];
    float sn = g_sn[gw];
    float4 v = *(const float4*)(S + (size_t)gw * OUT_DIM + lane * 4);
    float4 acc = make_float4(sn * v.x, sn * v.y, sn * v.z, sn * v.w);
    float cacc = sn;

    int p = beg;
    for (; p + 4 <= end; p += 4) {
        int2 e0 = g_adj[p], e1 = g_adj[p + 1], e2 = g_adj[p + 2], e3 = g_adj[p + 3];
        float w0 = __int_as_float(e0.y), w1 = __int_as_float(e1.y);
        float w2 = __int_as_float(e2.y), w3 = __int_as_float(e3.y);
        float4 u0 = *(const float4*)(S + (size_t)e0.x * OUT_DIM + lane * 4);
        float4 u1 = *(const float4*)(S + (size_t)e1.x * OUT_DIM + lane * 4);
        float4 u2 = *(const float4*)(S + (size_t)e2.x * OUT_DIM + lane * 4);
        float4 u3 = *(const float4*)(S + (size_t)e3.x * OUT_DIM + lane * 4);
        if (WRC) cacc += w0 + w1 + w2 + w3;
        acc.x += w0 * u0.x; acc.y += w0 * u0.y; acc.z += w0 * u0.z; acc.w += w0 * u0.w;
        acc.x += w1 * u1.x; acc.y += w1 * u1.y; acc.z += w1 * u1.z; acc.w += w1 * u1.w;
        acc.x += w2 * u2.x; acc.y += w2 * u2.y; acc.z += w2 * u2.z; acc.w += w2 * u2.w;
        acc.x += w3 * u3.x; acc.y += w3 * u3.y; acc.z += w3 * u3.z; acc.w += w3 * u3.w;
    }
    for (; p < end; p++) {
        int2 pr = g_adj[p];
        float w = __int_as_float(pr.y);
        if (WRC) cacc += w;
        float4 u = *(const float4*)(S + (size_t)pr.x * OUT_DIM + lane * 4);
        acc.x += w * u.x; acc.y += w * u.y; acc.z += w * u.z; acc.w += w * u.w;
    }

    if (WRC && lane == 0) g_c[gw] = cacc;

    if (CORR) {
        float ci = g_c[gw];
        int f = lane * 4;
        acc.x += ci * g_u2[f + 0] + b[f + 0];
        acc.y += ci * g_u2[f + 1] + b[f + 1];
        acc.z += ci * g_u2[f + 2] + b[f + 2];
        acc.w += ci * g_u2[f + 3] + b[f + 3];
    }
    *(float4*)(D + (size_t)gw * OUT_DIM + lane * 4) = acc;
}

// ---------------------------------------------------------------------------
static inline int ceil_div(int a, int b) { return (a + b - 1) / b; }

extern "C" void kernel_launch(void* const* d_in, const int* in_sizes, int n_in,
                              void* d_out, int out_size) {
    const float* features = (const float*)d_in[0];
    const void*  edge_idx = d_in[1];
    const float* W1       = (const float*)d_in[2];
    const float* b1       = (const float*)d_in[3];
    const float* W2       = (const float*)d_in[4];
    const float* b2       = (const float*)d_in[5];
    const float* b3       = (const float*)d_in[6];
    const float* b4       = (const float*)d_in[7];
    const float* head1    = (const float*)d_in[8];

    const int n = in_sizes[0] / IN_DIM;
    const int e = in_sizes[1] / 2;

    float* out = (float*)d_out;
    float* z_out  = out;
    float* h2_out = out + (size_t)n * OUT_DIM;
    float* h4_out = out + (size_t)n * OUT_DIM * 2;

    const int TPB = 256;
    dim3 blk(256);
    int aggb = ceil_div(n * 32, TPB);

    static cudaStream_t s1 = nullptr;
    static cudaEvent_t evFork = nullptr, evP = nullptr, evHW = nullptr,
                       evH2 = nullptr, evZ = nullptr;
    if (s1 == nullptr) {
        cudaStreamCreateWithFlags(&s1, cudaStreamNonBlocking);
        cudaEventCreateWithFlags(&evFork, cudaEventDisableTiming);
        cudaEventCreateWithFlags(&evP,    cudaEventDisableTiming);
        cudaEventCreateWithFlags(&evHW,   cudaEventDisableTiming);
        cudaEventCreateWithFlags(&evH2,   cudaEventDisableTiming);
        cudaEventCreateWithFlags(&evZ,    cudaEventDisableTiming);
    }

    // ---- fork ----
    cudaEventRecord(evFork, 0);
    cudaStreamWaitEvent(s1, evFork, 0);

    // s1: weights -> P -> HW21; later z (after h2).
    k_misc<<<6, 256, 0, s1>>>(W1, W2, b1, b3, head1);
    {
        dim3 grid(IN_DIM / 128, 2);
        k_w21<<<grid, blk, 0, s1>>>(W2, W1);
    }
    {
        dim3 grid(1, ceil_div(n, 64));   // P = X @ W21^T -> g_T
        k_mma<0, 3, 1, 0, 64><<<grid, blk, 0, s1>>>(n, OUT_DIM, IN_DIM, features,
                                                    nullptr, nullptr);
    }
    cudaEventRecord(evP, s1);
    {
        dim3 grid(IN_DIM / 128, 2);      // HW21t
        k_hw21<<<grid, blk, 0, s1>>>(head1);
    }
    cudaEventRecord(evHW, s1);

    // s0: CSR chain
    k_pre<<<ceil_div(n, TPB), TPB>>>((const int*)edge_idx, n);
    k_count<<<ceil_div(e, TPB), TPB>>>(edge_idx, e, n);
    k_scan<<<1, 1024>>>(n);
    k_fill<<<ceil_div(e, TPB), TPB>>>(edge_idx, e, n);

    // join for P
    cudaStreamWaitEvent(0, evP, 0);

    // ---- S1 = Ahat P -> g_H (computes c) ; h2 = Ahat S1 + c(x)u2 + b2 ----
    k_agg<1, 2, 0, 1><<<aggb, blk>>>(nullptr, nullptr, nullptr, n);
    k_agg<2, 0, 1, 0><<<aggb, blk>>>(nullptr, h2_out, b2, n);
    cudaEventRecord(evH2, 0);

    // s1: z = h2 @ head1 (parallel with aggs below)
    cudaStreamWaitEvent(s1, evH2, 0);
    {
        dim3 grid(1, ceil_div(n, 64));
        k_mma<0, 5, 0, 0, 64><<<grid, blk, 0, s1>>>(n, OUT_DIM, OUT_DIM, h2_out,
                                                    z_out, nullptr);
    }
    cudaEventRecord(evZ, s1);

    // ---- S2 = Ahat h2 -> g_T ; R = Ahat S2 -> g_H ----
    k_agg<0, 1, 0, 0><<<aggb, blk>>>(h2_out, nullptr, nullptr, n);
    k_agg<1, 2, 0, 0><<<aggb, blk>>>(nullptr, nullptr, nullptr, n);

    // ---- h4 = R @ HW21 + c(x)u4 + b4 ----
    cudaStreamWaitEvent(0, evHW, 0);
    {
        dim3 grid(IN_DIM / 128, ceil_div(n, 128));
        k_mma<2, 4, 0, 1, 128><<<grid, blk>>>(n, IN_DIM, OUT_DIM, nullptr,
                                              h4_out, b4);
    }

    // join z before capture end
    cudaStreamWaitEvent(0, evZ, 0);

    (void)n_in; (void)out_size;
}

// round 14
// speedup vs baseline: 1.2149x; 1.1080x over previous
#include <cuda_runtime.h>
#include <cuda_fp16.h>
#include <cstdint>

// ---------------------------------------------------------------------------
// GAE 4-layer GCN autoencoder: algebraic fusion + fp16 CSR-gather pipeline +
// fp16 mma GEMMs. All intermediates (P, S1, h2copy, S2, R) are half; final
// outputs fp32.
// ---------------------------------------------------------------------------

#define N_NODES 20000
#define IN_DIM  1024
#define HID_DIM 512
#define OUT_DIM 128
#define N_EDGES 160000

__device__ alignas(16) __half g_Th[(size_t)N_NODES * OUT_DIM];      // P / S2
__device__ alignas(16) __half g_Hh[(size_t)N_NODES * OUT_DIM];      // S1 / R
__device__ alignas(16) __half g_Zh[(size_t)N_NODES * OUT_DIM];      // h2 half copy
__device__ alignas(16) float  g_W21[(size_t)OUT_DIM * IN_DIM];      // fp32 (for hw21)
__device__ alignas(16) __half g_W21h[(size_t)OUT_DIM * IN_DIM];     // [128,1024] n-major
__device__ alignas(16) __half g_HW21th[(size_t)IN_DIM * OUT_DIM];   // [1024,128] n-major
__device__ alignas(16) __half g_Hth[(size_t)OUT_DIM * OUT_DIM];     // head1^T
__device__ alignas(16) float  g_u2[OUT_DIM];
__device__ alignas(16) float  g_u4[IN_DIM];
__device__ float g_dinv[N_NODES];
__device__ float g_sn[N_NODES];
__device__ float g_c[N_NODES];
__device__ int   g_cnt[N_NODES];
__device__ int   g_off[N_NODES + 1];
__device__ int   g_cur[N_NODES];
__device__ int2  g_adj[N_EDGES];
__device__ int   g_is64;

// half buffer selectors: 1 g_Th, 2 g_Hh, 3 g_Zh
template <int SEL>
__device__ __forceinline__ const __half* pickhb() {
    if (SEL == 1) return g_Th;
    if (SEL == 2) return g_Hh;
    return g_Zh;
}
template <int SEL>
__device__ __forceinline__ __half* pickhbw() {
    if (SEL == 1) return g_Th;
    if (SEL == 2) return g_Hh;
    return g_Zh;
}
// mma B selectors: 3 g_W21h, 4 g_HW21th, 5 g_Hth
template <int SEL>
__device__ __forceinline__ const __half* pickB() {
    if (SEL == 3) return g_W21h;
    if (SEL == 4) return g_HW21th;
    return g_Hth;
}

__device__ __forceinline__ float4 h4f(uint2 r) {
    __half2 a = *(__half2*)&r.x, b = *(__half2*)&r.y;
    float2 f0 = __half22float2(a), f1 = __half22float2(b);
    return make_float4(f0.x, f0.y, f1.x, f1.y);
}
__device__ __forceinline__ uint2 f4h(float4 v) {
    __half2 a = __floats2half2_rn(v.x, v.y);
    __half2 b = __floats2half2_rn(v.z, v.w);
    uint2 r;
    r.x = *(unsigned*)&a; r.y = *(unsigned*)&b;
    return r;
}

// ---------------------------------------------------------------------------
// probe dtype + zero counters
// ---------------------------------------------------------------------------
__global__ void k_pre(const int* __restrict__ ei32, int n) {
    int i = blockIdx.x * blockDim.x + threadIdx.x;
    if (i == 0) {
        int z = (ei32[1] == 0) & (ei32[3] == 0) & (ei32[5] == 0) &
                (ei32[7] == 0) & (ei32[9] == 0) & (ei32[11] == 0);
        g_is64 = z;
    }
    if (i < n) g_cnt[i] = 0;
}

__device__ __forceinline__ int load_idx(const void* ei, int e_cnt, int row, int e) {
    if (g_is64) return (int)((const long long*)ei)[(size_t)row * e_cnt + e];
    return ((const int*)ei)[(size_t)row * e_cnt + e];
}

__global__ void k_count(const void* __restrict__ ei, int e_cnt, int n) {
    int e = blockIdx.x * blockDim.x + threadIdx.x;
    if (e < e_cnt) {
        int d = load_idx(ei, e_cnt, 1, e);
        if ((unsigned)d < (unsigned)n) atomicAdd(&g_cnt[d], 1);
    }
}

// ---------------------------------------------------------------------------
// Single-pass scan (+ dinv/sn)
// ---------------------------------------------------------------------------
#define SCAN_CHUNK ((N_NODES + 1023) / 1024)

__global__ __launch_bounds__(1024)
void k_scan(int n) {
    int tid = threadIdx.x;
    int lane = tid & 31, wid = tid >> 5;
    int base = tid * SCAN_CHUNK;
    int vloc[SCAN_CHUNK];
    int s = 0;
#pragma unroll
    for (int j = 0; j < SCAN_CHUNK; j++) {
        int i = base + j;
        int v = (i < n) ? g_cnt[i] : 0;
        vloc[j] = v;
        s += v;
    }
    int x = s;
#pragma unroll
    for (int d = 1; d < 32; d <<= 1) {
        int y = __shfl_up_sync(0xFFFFFFFFu, x, d);
        if (lane >= d) x += y;
    }
    __shared__ int ws[32];
    if (lane == 31) ws[wid] = x;
    __syncthreads();
    if (wid == 0) {
        int w = ws[lane];
#pragma unroll
        for (int d = 1; d < 32; d <<= 1) {
            int y = __shfl_up_sync(0xFFFFFFFFu, w, d);
            if (lane >= d) w += y;
        }
        ws[lane] = w;
    }
    __syncthreads();
    int excl = x - s + ((wid > 0) ? ws[wid - 1] : 0);
    if (tid == 0) g_off[0] = 0;
#pragma unroll
    for (int j = 0; j < SCAN_CHUNK; j++) {
        int i = base + j;
        if (i < n) {
            g_cur[i] = excl;
            excl += vloc[j];
            g_off[i + 1] = excl;
            float r = rsqrtf((float)(vloc[j] + 1));
            g_dinv[i] = r;
            g_sn[i] = r * r;
        }
    }
}

__global__ void k_fill(const void* __restrict__ ei, int e_cnt, int n) {
    int e = blockIdx.x * blockDim.x + threadIdx.x;
    if (e < e_cnt) {
        int s = load_idx(ei, e_cnt, 0, e);
        int d = load_idx(ei, e_cnt, 1, e);
        if ((unsigned)s >= (unsigned)n) s = 0;
        if ((unsigned)d >= (unsigned)n) d = 0;
        float w = g_dinv[s] * g_dinv[d];
        int pos = atomicAdd(&g_cur[d], 1);
        g_adj[pos] = make_int2(s, __float_as_int(w));
    }
}

// ---------------------------------------------------------------------------
// misc: u4 (blocks 0..15, k-split + smem reduce), u2 (block 16), Hth (block 17)
// ---------------------------------------------------------------------------
__global__ void k_misc(const float* __restrict__ W1, const float* __restrict__ W2,
                       const float* __restrict__ b1, const float* __restrict__ b3,
                       const float* __restrict__ head1) {
    int b = blockIdx.x;
    __shared__ float red[256];
    if (b < 16) {
        int fl = threadIdx.x & 63;
        int kg = threadIdx.x >> 6;      // 0..3
        int f = b * 64 + fl;
        float s = 0.f;
        for (int k = kg * 128; k < kg * 128 + 128; k++)
            s += b3[k] * W1[(size_t)k * IN_DIM + f];
        red[threadIdx.x] = s;
        __syncthreads();
        if (threadIdx.x < 64)
            g_u4[b * 64 + threadIdx.x] = red[threadIdx.x] + red[64 + threadIdx.x] +
                                         red[128 + threadIdx.x] + red[192 + threadIdx.x];
    } else if (b == 16) {
        int o = threadIdx.x & 127;
        int kg = threadIdx.x >> 7;      // 0..1
        float s = 0.f;
        for (int k = kg * 256; k < kg * 256 + 256; k++)
            s += W2[(size_t)o * HID_DIM + k] * b1[k];
        red[threadIdx.x] = s;
        __syncthreads();
        if (threadIdx.x < 128)
            g_u2[threadIdx.x] = red[threadIdx.x] + red[128 + threadIdx.x];
    } else {
        for (int idx = threadIdx.x; idx < OUT_DIM * OUT_DIM; idx += 256) {
            int r = idx >> 7, c = idx & 127;
            g_Hth[(size_t)c * OUT_DIM + r] = __float2half(head1[idx]);
        }
    }
}

// ---------------------------------------------------------------------------
// W21 = W2 @ W1 (fp32 FFMA, K=512) -> g_W21 fp32 + g_W21h half.
// grid (IN_DIM/128, 2), BM=64, BN=128, BK=8.
// ---------------------------------------------------------------------------
__global__ __launch_bounds__(256)
void k_w21(const float* __restrict__ A, const float* __restrict__ B) {
    __shared__ float As[8][64];
    __shared__ float Bs[8][128];
    const int bx = blockIdx.x;
    const int by = blockIdx.y;
    const int tid = threadIdx.x;
    const int tcol = tid % 16;
    const int trow = tid / 16;

    float acc[4][8];
#pragma unroll
    for (int i = 0; i < 4; i++)
#pragma unroll
        for (int j = 0; j < 8; j++) acc[i][j] = 0.0f;

    for (int k0 = 0; k0 < HID_DIM; k0 += 8) {
        if (tid < 128) {
            int aRow = tid >> 1;
            int aCol = (tid & 1) << 2;
            int m = by * 64 + aRow;
            float4 av = *(const float4*)(A + (size_t)m * HID_DIM + k0 + aCol);
            As[aCol + 0][aRow] = av.x;
            As[aCol + 1][aRow] = av.y;
            As[aCol + 2][aRow] = av.z;
            As[aCol + 3][aRow] = av.w;
        }
        {
            int kk = tid >> 5;
            int nn = (tid & 31) << 2;
            float4 bv = *(const float4*)(B + (size_t)(k0 + kk) * IN_DIM + bx * 128 + nn);
            *(float4*)&Bs[kk][nn] = bv;
        }
        __syncthreads();
#pragma unroll
        for (int k = 0; k < 8; k++) {
            float ra[4], rb[8];
#pragma unroll
            for (int i = 0; i < 4; i++) ra[i] = As[k][trow * 4 + i];
#pragma unroll
            for (int j = 0; j < 8; j++) rb[j] = Bs[k][tcol * 8 + j];
#pragma unroll
            for (int i = 0; i < 4; i++)
#pragma unroll
                for (int j = 0; j < 8; j++) acc[i][j] += ra[i] * rb[j];
        }
        __syncthreads();
    }
#pragma unroll
    for (int i = 0; i < 4; i++) {
        int m = by * 64 + trow * 4 + i;
#pragma unroll
        for (int j = 0; j < 8; j++) {
            int col = bx * 128 + tcol * 8 + j;
            g_W21[(size_t)m * IN_DIM + col]  = acc[i][j];
            g_W21h[(size_t)m * IN_DIM + col] = __float2half(acc[i][j]);
        }
    }
}

// ---------------------------------------------------------------------------
// HW21 = head1 @ W21 [128,1024] (fp32 FFMA, K=128) -> g_HW21th half transposed.
// ---------------------------------------------------------------------------
__global__ __launch_bounds__(256)
void k_hw21(const float* __restrict__ head1) {
    __shared__ float As[8][64];
    __shared__ float Bs[8][128];
    const int bx = blockIdx.x;
    const int by = blockIdx.y;
    const int tid = threadIdx.x;
    const int tcol = tid % 16;
    const int trow = tid / 16;

    float acc[4][8];
#pragma unroll
    for (int i = 0; i < 4; i++)
#pragma unroll
        for (int j = 0; j < 8; j++) acc[i][j] = 0.0f;

    for (int k0 = 0; k0 < OUT_DIM; k0 += 8) {
        if (tid < 128) {
            int aRow = tid >> 1;
            int aCol = (tid & 1) << 2;
            int m = by * 64 + aRow;
            float4 av = *(const float4*)(head1 + (size_t)m * OUT_DIM + k0 + aCol);
            As[aCol + 0][aRow] = av.x;
            As[aCol + 1][aRow] = av.y;
            As[aCol + 2][aRow] = av.z;
            As[aCol + 3][aRow] = av.w;
        }
        {
            int kk = tid >> 5;
            int nn = (tid & 31) << 2;
            float4 bv = *(const float4*)(g_W21 + (size_t)(k0 + kk) * IN_DIM + bx * 128 + nn);
            *(float4*)&Bs[kk][nn] = bv;
        }
        __syncthreads();
#pragma unroll
        for (int k = 0; k < 8; k++) {
            float ra[4], rb[8];
#pragma unroll
            for (int i = 0; i < 4; i++) ra[i] = As[k][trow * 4 + i];
#pragma unroll
            for (int j = 0; j < 8; j++) rb[j] = Bs[k][tcol * 8 + j];
#pragma unroll
            for (int i = 0; i < 4; i++)
#pragma unroll
                for (int j = 0; j < 8; j++) acc[i][j] += ra[i] * rb[j];
        }
        __syncthreads();
    }
#pragma unroll
    for (int i = 0; i < 4; i++) {
        int m = by * 64 + trow * 4 + i;
#pragma unroll
        for (int j = 0; j < 8; j++) {
            int col = bx * 128 + tcol * 8 + j;
            g_HW21th[(size_t)col * OUT_DIM + m] = __float2half(acc[i][j]);
        }
    }
}

// ---------------------------------------------------------------------------
// fp16 tensor-core GEMM (TN form), m16n8k16, register-prefetch pipelined.
//   AMODE: 0 = fp32 ext (cvt), 1 = g_Zh half, 2 = g_Hh half.
//   CH: 1 -> C = g_Th (half); 0 -> C = Cext fp32.
//   + bias[n] + CORR4 (c[m]*u4[n]). BMv in {64,128}, BN=128, BK=32, 8 warps.
// ---------------------------------------------------------------------------
template <int AMODE, int BSEL, int CH, int CORR4, int BMv>
__global__ __launch_bounds__(256)
void k_mma(int M, int Nn, int K,
           const float* __restrict__ Aext,
           float* __restrict__ Cext,
           const float* __restrict__ bias) {
    constexpr int MT  = BMv / 32;
    constexpr int AR4 = BMv / 32;   // fp32-A: float4/thread; half-A: uint4/thread = BMv/64
    const __half* B = pickB<BSEL>();

    __shared__ __half As[BMv][40];
    __shared__ __half Bs[128][40];

    const int tid  = threadIdx.x;
    const int lane = tid & 31;
    const int wid  = tid >> 5;
    const int g    = lane >> 2;
    const int t    = lane & 3;
    const int wm   = (wid & 1) * (BMv / 2);
    const int wn   = (wid >> 1) * 32;
    const int bx   = blockIdx.x;
    const int by   = blockIdx.y;

    float4 ar[AR4];          // fp32-A staging
    uint4  arh[(BMv + 63) / 64];  // half-A staging
    uint4  br4[2];

    const __half* Ah = (AMODE == 1) ? g_Zh : g_Hh;

    auto loadA = [&](int k0) {
        if (AMODE == 0) {
#pragma unroll
            for (int i = 0; i < AR4; i++) {
                int f4 = tid + i * 256;
                int m  = f4 >> 3;
                int kq = (f4 & 7) << 2;
                int gm = by * BMv + m;
                ar[i] = (gm < M) ? *(const float4*)(Aext + (size_t)gm * K + k0 + kq)
                                 : make_float4(0.f, 0.f, 0.f, 0.f);
            }
        } else {
#pragma unroll
            for (int i = 0; i < (BMv + 63) / 64; i++) {
                int u  = tid + i * 256;
                int m  = u >> 2;
                int kq = (u & 3) << 3;
                int gm = by * BMv + m;
                arh[i] = (gm < M) ? *(const uint4*)(Ah + (size_t)gm * K + k0 + kq)
                                  : make_uint4(0, 0, 0, 0);
            }
        }
    };
    auto loadB = [&](int k0) {
#pragma unroll
        for (int i = 0; i < 2; i++) {
            int f4 = tid + i * 256;
            int nn = f4 >> 2;
            int kq = (f4 & 3) << 3;
            br4[i] = *(const uint4*)(B + (size_t)(bx * 128 + nn) * K + k0 + kq);
        }
    };
    auto storeA = [&]() {
        if (AMODE == 0) {
#pragma unroll
            for (int i = 0; i < AR4; i++) {
                int f4 = tid + i * 256;
                int m  = f4 >> 3;
                int kq = (f4 & 7) << 2;
                __half2 h01 = __floats2half2_rn(ar[i].x, ar[i].y);
                __half2 h23 = __floats2half2_rn(ar[i].z, ar[i].w);
                *(__half2*)&As[m][kq]     = h01;
                *(__half2*)&As[m][kq + 2] = h23;
            }
        } else {
#pragma unroll
            for (int i = 0; i < (BMv + 63) / 64; i++) {
                int u  = tid + i * 256;
                int m  = u >> 2;
                int kq = (u & 3) << 3;
                *(uint4*)&As[m][kq] = arh[i];
            }
        }
    };
    auto storeB = [&]() {
#pragma unroll
        for (int i = 0; i < 2; i++) {
            int f4 = tid + i * 256;
            int nn = f4 >> 2;
            int kq = (f4 & 3) << 3;
            *(uint4*)&Bs[nn][kq] = br4[i];
        }
    };

    float c[MT][4][4];
#pragma unroll
    for (int i = 0; i < MT; i++)
#pragma unroll
        for (int j = 0; j < 4; j++)
#pragma unroll
            for (int r = 0; r < 4; r++) c[i][j][r] = 0.0f;

    const int nt = K / 32;
    loadA(0); loadB(0);
    storeA(); storeB();
    __syncthreads();

    for (int it = 0; it < nt; it++) {
        if (it + 1 < nt) { loadA((it + 1) * 32); loadB((it + 1) * 32); }

#pragma unroll
        for (int ks = 0; ks < 2; ks++) {
            unsigned a[MT][4], b[4][2];
            int kb = ks * 16 + 2 * t;
#pragma unroll
            for (int i = 0; i < MT; i++) {
                int mr = wm + i * 16 + g;
                a[i][0] = *(const unsigned*)&As[mr    ][kb    ];
                a[i][1] = *(const unsigned*)&As[mr + 8][kb    ];
                a[i][2] = *(const unsigned*)&As[mr    ][kb + 8];
                a[i][3] = *(const unsigned*)&As[mr + 8][kb + 8];
            }
#pragma unroll
            for (int j = 0; j < 4; j++) {
                int nr = wn + j * 8 + g;
                b[j][0] = *(const unsigned*)&Bs[nr][kb    ];
                b[j][1] = *(const unsigned*)&Bs[nr][kb + 8];
            }
#pragma unroll
            for (int i = 0; i < MT; i++)
#pragma unroll
                for (int j = 0; j < 4; j++) {
                    asm volatile(
                        "mma.sync.aligned.m16n8k16.row.col.f32.f16.f16.f32 "
                        "{%0,%1,%2,%3}, {%4,%5,%6,%7}, {%8,%9}, {%0,%1,%2,%3};"
                        : "+f"(c[i][j][0]), "+f"(c[i][j][1]),
                          "+f"(c[i][j][2]), "+f"(c[i][j][3])
                        : "r"(a[i][0]), "r"(a[i][1]), "r"(a[i][2]), "r"(a[i][3]),
                          "r"(b[j][0]), "r"(b[j][1]));
                }
        }
        __syncthreads();
        if (it + 1 < nt) {
            storeA(); storeB();
            __syncthreads();
        }
    }

#pragma unroll
    for (int j = 0; j < 4; j++) {
        int cn = bx * 128 + wn + j * 8 + t * 2;
        float e0 = bias ? bias[cn]     : 0.0f;
        float e1 = bias ? bias[cn + 1] : 0.0f;
        float u40 = CORR4 ? g_u4[cn]     : 0.0f;
        float u41 = CORR4 ? g_u4[cn + 1] : 0.0f;
#pragma unroll
        for (int i = 0; i < MT; i++) {
            int r0 = by * BMv + wm + i * 16 + g;
            if (r0 < M) {
                float a0 = c[i][j][0] + e0, a1 = c[i][j][1] + e1;
                if (CORR4) { float ci = g_c[r0]; a0 += ci * u40; a1 += ci * u41; }
                if (CH) {
                    __half2 h = __floats2half2_rn(a0, a1);
                    *(__half2*)(g_Th + (size_t)r0 * Nn + cn) = h;
                } else {
                    *(float2*)(Cext + (size_t)r0 * Nn + cn) = make_float2(a0, a1);
                }
            }
            int r1 = r0 + 8;
            if (r1 < M) {
                float a2 = c[i][j][2] + e0, a3 = c[i][j][3] + e1;
                if (CORR4) { float ci = g_c[r1]; a2 += ci * u40; a3 += ci * u41; }
                if (CH) {
                    __half2 h = __floats2half2_rn(a2, a3);
                    *(__half2*)(g_Th + (size_t)r1 * Nn + cn) = h;
                } else {
                    *(float2*)(Cext + (size_t)r1 * Nn + cn) = make_float2(a2, a3);
                }
            }
        }
    }
}

// ---------------------------------------------------------------------------
// Aggregation (warp-per-node CSR gather) over HALF sources, fp32 accumulate.
//   SMODE: half src buffer (1 g_Th, 2 g_Hh, 3 g_Zh)
//   DMODE: 1/2 -> half dst buffer; 0 -> fp32 ext dst + half copy to g_Zh
//   WRC=1: writes g_c; CORR=1: adds c[i]*u2[f] + b[f]
// ---------------------------------------------------------------------------
template <int SMODE, int DMODE, int CORR, int WRC>
__global__ __launch_bounds__(256)
void k_agg(float* __restrict__ Dext,
           const float* __restrict__ b,
           int n) {
    int gw = (blockIdx.x * 256 + threadIdx.x) >> 5;
    if (gw >= n) return;
    int lane = threadIdx.x & 31;
    const __half* S = pickhb<SMODE>();

    int beg = g_off[gw];
    int end = g_off[gw + 1];
    float sn = g_sn[gw];
    int lo = lane * 4;
    float4 v = h4f(*(const uint2*)(S + (size_t)gw * OUT_DIM + lo));
    float4 acc = make_float4(sn * v.x, sn * v.y, sn * v.z, sn * v.w);
    float cacc = sn;

    int p = beg;
    for (; p + 4 <= end; p += 4) {
        int2 e0 = g_adj[p], e1 = g_adj[p + 1], e2 = g_adj[p + 2], e3 = g_adj[p + 3];
        float w0 = __int_as_float(e0.y), w1 = __int_as_float(e1.y);
        float w2 = __int_as_float(e2.y), w3 = __int_as_float(e3.y);
        float4 u0 = h4f(*(const uint2*)(S + (size_t)e0.x * OUT_DIM + lo));
        float4 u1 = h4f(*(const uint2*)(S + (size_t)e1.x * OUT_DIM + lo));
        float4 u2v = h4f(*(const uint2*)(S + (size_t)e2.x * OUT_DIM + lo));
        float4 u3 = h4f(*(const uint2*)(S + (size_t)e3.x * OUT_DIM + lo));
        if (WRC) cacc += w0 + w1 + w2 + w3;
        acc.x += w0 * u0.x; acc.y += w0 * u0.y; acc.z += w0 * u0.z; acc.w += w0 * u0.w;
        acc.x += w1 * u1.x; acc.y += w1 * u1.y; acc.z += w1 * u1.z; acc.w += w1 * u1.w;
        acc.x += w2 * u2v.x; acc.y += w2 * u2v.y; acc.z += w2 * u2v.z; acc.w += w2 * u2v.w;
        acc.x += w3 * u3.x; acc.y += w3 * u3.y; acc.z += w3 * u3.z; acc.w += w3 * u3.w;
    }
    for (; p < end; p++) {
        int2 pr = g_adj[p];
        float w = __int_as_float(pr.y);
        if (WRC) cacc += w;
        float4 u = h4f(*(const uint2*)(S + (size_t)pr.x * OUT_DIM + lo));
        acc.x += w * u.x; acc.y += w * u.y; acc.z += w * u.z; acc.w += w * u.w;
    }

    if (WRC && lane == 0) g_c[gw] = cacc;

    if (CORR) {
        float ci = g_c[gw];
        acc.x += ci * g_u2[lo + 0] + b[lo + 0];
        acc.y += ci * g_u2[lo + 1] + b[lo + 1];
        acc.z += ci * g_u2[lo + 2] + b[lo + 2];
        acc.w += ci * g_u2[lo + 3] + b[lo + 3];
    }

    if (DMODE == 0) {
        *(float4*)(Dext + (size_t)gw * OUT_DIM + lo) = acc;
        *(uint2*)(g_Zh + (size_t)gw * OUT_DIM + lo) = f4h(acc);
    } else {
        __half* D = pickhbw<DMODE>();
        *(uint2*)(D + (size_t)gw * OUT_DIM + lo) = f4h(acc);
    }
}

// ---------------------------------------------------------------------------
static inline int ceil_div(int a, int b) { return (a + b - 1) / b; }

extern "C" void kernel_launch(void* const* d_in, const int* in_sizes, int n_in,
                              void* d_out, int out_size) {
    const float* features = (const float*)d_in[0];
    const void*  edge_idx = d_in[1];
    const float* W1       = (const float*)d_in[2];
    const float* b1       = (const float*)d_in[3];
    const float* W2       = (const float*)d_in[4];
    const float* b2       = (const float*)d_in[5];
    const float* b3       = (const float*)d_in[6];
    const float* b4       = (const float*)d_in[7];
    const float* head1    = (const float*)d_in[8];

    const int n = in_sizes[0] / IN_DIM;
    const int e = in_sizes[1] / 2;

    float* out = (float*)d_out;
    float* z_out  = out;
    float* h2_out = out + (size_t)n * OUT_DIM;
    float* h4_out = out + (size_t)n * OUT_DIM * 2;

    const int TPB = 256;
    dim3 blk(256);
    int aggb = ceil_div(n * 32, TPB);

    static cudaStream_t s1 = nullptr;
    static cudaEvent_t evFork = nullptr, evP = nullptr, evAux = nullptr,
                       evHW = nullptr, evH2 = nullptr, evZ = nullptr;
    if (s1 == nullptr) {
        cudaStreamCreateWithFlags(&s1, cudaStreamNonBlocking);
        cudaEventCreateWithFlags(&evFork, cudaEventDisableTiming);
        cudaEventCreateWithFlags(&evP,    cudaEventDisableTiming);
        cudaEventCreateWithFlags(&evAux,  cudaEventDisableTiming);
        cudaEventCreateWithFlags(&evHW,   cudaEventDisableTiming);
        cudaEventCreateWithFlags(&evH2,   cudaEventDisableTiming);
        cudaEventCreateWithFlags(&evZ,    cudaEventDisableTiming);
    }

    // ---- fork ----
    cudaEventRecord(evFork, 0);
    cudaStreamWaitEvent(s1, evFork, 0);

    // s1: w21 -> P (critical) ; then misc, hw21 (off critical path)
    {
        dim3 grid(IN_DIM / 128, 2);
        k_w21<<<grid, blk, 0, s1>>>(W2, W1);
    }
    {
        dim3 grid(1, ceil_div(n, 64));   // P = X @ W21^T -> g_Th (half)
        k_mma<0, 3, 1, 0, 64><<<grid, blk, 0, s1>>>(n, OUT_DIM, IN_DIM, features,
                                                    nullptr, nullptr);
    }
    cudaEventRecord(evP, s1);
    k_misc<<<18, 256, 0, s1>>>(W1, W2, b1, b3, head1);
    cudaEventRecord(evAux, s1);
    {
        dim3 grid(IN_DIM / 128, 2);
        k_hw21<<<grid, blk, 0, s1>>>(head1);
    }
    cudaEventRecord(evHW, s1);

    // s0: CSR chain
    k_pre<<<ceil_div(n, TPB), TPB>>>((const int*)edge_idx, n);
    k_count<<<ceil_div(e, TPB), TPB>>>(edge_idx, e, n);
    k_scan<<<1, 1024>>>(n);
    k_fill<<<ceil_div(e, TPB), TPB>>>(edge_idx, e, n);

    cudaStreamWaitEvent(0, evP, 0);

    // ---- S1 = Ahat P -> g_Hh (computes c) ----
    k_agg<1, 2, 0, 1><<<aggb, blk>>>(nullptr, nullptr, n);

    // ---- h2 = Ahat S1 + c(x)u2 + b2 -> h2_out (+half copy g_Zh) ----
    cudaStreamWaitEvent(0, evAux, 0);   // u2
    k_agg<2, 0, 1, 0><<<aggb, blk>>>(h2_out, b2, n);
    cudaEventRecord(evH2, 0);

    // s1: z = (h2 half) @ head1 -> z_out  (parallel with aggs below)
    cudaStreamWaitEvent(s1, evH2, 0);
    {
        dim3 grid(1, ceil_div(n, 64));
        k_mma<1, 5, 0, 0, 64><<<grid, blk, 0, s1>>>(n, OUT_DIM, OUT_DIM, nullptr,
                                                    z_out, nullptr);
    }
    cudaEventRecord(evZ, s1);

    // ---- S2 = Ahat h2 -> g_Th ; R = Ahat S2 -> g_Hh ----
    k_agg<3, 1, 0, 0><<<aggb, blk>>>(nullptr, nullptr, n);
    k_agg<1, 2, 0, 0><<<aggb, blk>>>(nullptr, nullptr, n);

    // ---- h4 = R @ HW21 + c(x)u4 + b4 -> h4_out ----
    cudaStreamWaitEvent(0, evHW, 0);
    {
        dim3 grid(IN_DIM / 128, ceil_div(n, 128));
        k_mma<2, 4, 0, 1, 128><<<grid, blk>>>(n, IN_DIM, OUT_DIM, nullptr,
                                              h4_out, b4);
    }

    cudaStreamWaitEvent(0, evZ, 0);

    (void)n_in; (void)out_size;
}

// round 15
// speedup vs baseline: 1.2339x; 1.0156x over previous
#include <cuda_runtime.h>
#include <cuda_fp16.h>
#include <cstdint>

// ---------------------------------------------------------------------------
// GAE 4-layer GCN autoencoder: algebraic fusion + fp16 CSR-gather pipeline +
// fp16 mma GEMMs. This round: k_pre folded away, w21 grid widened, MLP-8 aggs.
// ---------------------------------------------------------------------------

#define N_NODES 20000
#define IN_DIM  1024
#define HID_DIM 512
#define OUT_DIM 128
#define N_EDGES 160000

__device__ alignas(16) __half g_Th[(size_t)N_NODES * OUT_DIM];      // P / S2
__device__ alignas(16) __half g_Hh[(size_t)N_NODES * OUT_DIM];      // S1 / R
__device__ alignas(16) __half g_Zh[(size_t)N_NODES * OUT_DIM];      // h2 half copy
__device__ alignas(16) float  g_W21[(size_t)OUT_DIM * IN_DIM];      // fp32 (for hw21)
__device__ alignas(16) __half g_W21h[(size_t)OUT_DIM * IN_DIM];     // [128,1024] n-major
__device__ alignas(16) __half g_HW21th[(size_t)IN_DIM * OUT_DIM];   // [1024,128] n-major
__device__ alignas(16) __half g_Hth[(size_t)OUT_DIM * OUT_DIM];     // head1^T
__device__ alignas(16) float  g_u2[OUT_DIM];
__device__ alignas(16) float  g_u4[IN_DIM];
__device__ float g_dinv[N_NODES];
__device__ float g_sn[N_NODES];
__device__ float g_c[N_NODES];
__device__ int   g_cnt[N_NODES];     // invariant: zero at kernel_launch entry
__device__ int   g_off[N_NODES + 1];
__device__ int   g_cur[N_NODES];
__device__ int2  g_adj[N_EDGES];

// half buffer selectors: 1 g_Th, 2 g_Hh, 3 g_Zh
template <int SEL>
__device__ __forceinline__ const __half* pickhb() {
    if (SEL == 1) return g_Th;
    if (SEL == 2) return g_Hh;
    return g_Zh;
}
template <int SEL>
__device__ __forceinline__ __half* pickhbw() {
    if (SEL == 1) return g_Th;
    if (SEL == 2) return g_Hh;
    return g_Zh;
}
// mma B selectors: 3 g_W21h, 4 g_HW21th, 5 g_Hth
template <int SEL>
__device__ __forceinline__ const __half* pickB() {
    if (SEL == 3) return g_W21h;
    if (SEL == 4) return g_HW21th;
    return g_Hth;
}

__device__ __forceinline__ float4 h4f(uint2 r) {
    __half2 a = *(__half2*)&r.x, b = *(__half2*)&r.y;
    float2 f0 = __half22float2(a), f1 = __half22float2(b);
    return make_float4(f0.x, f0.y, f1.x, f1.y);
}
__device__ __forceinline__ uint2 f4h(float4 v) {
    __half2 a = __floats2half2_rn(v.x, v.y);
    __half2 b = __floats2half2_rn(v.z, v.w);
    uint2 r;
    r.x = *(unsigned*)&a; r.y = *(unsigned*)&b;
    return r;
}

// int64-detection: int64 indices < 2^31 have zero odd int32 words (cached loads)
__device__ __forceinline__ int probe64(const int* __restrict__ ei32) {
    return (ei32[1] == 0) & (ei32[3] == 0) & (ei32[5] == 0) &
           (ei32[7] == 0) & (ei32[9] == 0) & (ei32[11] == 0);
}
__device__ __forceinline__ int load_idx64(const void* ei, int is64, int e_cnt,
                                          int row, int e) {
    if (is64) return (int)((const long long*)ei)[(size_t)row * e_cnt + e];
    return ((const int*)ei)[(size_t)row * e_cnt + e];
}

// ---------------------------------------------------------------------------
// CSR: count (g_cnt must be zero at entry; k_scan restores it)
// ---------------------------------------------------------------------------
__global__ void k_count(const void* __restrict__ ei, int e_cnt, int n) {
    int e = blockIdx.x * blockDim.x + threadIdx.x;
    int is64 = probe64((const int*)ei);
    if (e < e_cnt) {
        int d = load_idx64(ei, is64, e_cnt, 1, e);
        if ((unsigned)d < (unsigned)n) atomicAdd(&g_cnt[d], 1);
    }
}

// ---------------------------------------------------------------------------
// Single-pass scan (+ dinv/sn) ; re-zeros g_cnt for the next call.
// ---------------------------------------------------------------------------
#define SCAN_CHUNK ((N_NODES + 1023) / 1024)

__global__ __launch_bounds__(1024)
void k_scan(int n) {
    int tid = threadIdx.x;
    int lane = tid & 31, wid = tid >> 5;
    int base = tid * SCAN_CHUNK;
    int vloc[SCAN_CHUNK];
    int s = 0;
#pragma unroll
    for (int j = 0; j < SCAN_CHUNK; j++) {
        int i = base + j;
        int v = (i < n) ? g_cnt[i] : 0;
        vloc[j] = v;
        s += v;
    }
    int x = s;
#pragma unroll
    for (int d = 1; d < 32; d <<= 1) {
        int y = __shfl_up_sync(0xFFFFFFFFu, x, d);
        if (lane >= d) x += y;
    }
    __shared__ int ws[32];
    if (lane == 31) ws[wid] = x;
    __syncthreads();
    if (wid == 0) {
        int w = ws[lane];
#pragma unroll
        for (int d = 1; d < 32; d <<= 1) {
            int y = __shfl_up_sync(0xFFFFFFFFu, w, d);
            if (lane >= d) w += y;
        }
        ws[lane] = w;
    }
    __syncthreads();
    int excl = x - s + ((wid > 0) ? ws[wid - 1] : 0);
    if (tid == 0) g_off[0] = 0;
#pragma unroll
    for (int j = 0; j < SCAN_CHUNK; j++) {
        int i = base + j;
        if (i < n) {
            g_cur[i] = excl;
            excl += vloc[j];
            g_off[i + 1] = excl;
            float r = rsqrtf((float)(vloc[j] + 1));
            g_dinv[i] = r;
            g_sn[i] = r * r;
            g_cnt[i] = 0;   // restore invariant for next call
        }
    }
}

__global__ void k_fill(const void* __restrict__ ei, int e_cnt, int n) {
    int e = blockIdx.x * blockDim.x + threadIdx.x;
    int is64 = probe64((const int*)ei);
    if (e < e_cnt) {
        int s = load_idx64(ei, is64, e_cnt, 0, e);
        int d = load_idx64(ei, is64, e_cnt, 1, e);
        if ((unsigned)s >= (unsigned)n) s = 0;
        if ((unsigned)d >= (unsigned)n) d = 0;
        float w = g_dinv[s] * g_dinv[d];
        int pos = atomicAdd(&g_cur[d], 1);
        g_adj[pos] = make_int2(s, __float_as_int(w));
    }
}

// ---------------------------------------------------------------------------
// misc: u4 (blocks 0..15, k-split + smem reduce), u2 (block 16), Hth (block 17)
// ---------------------------------------------------------------------------
__global__ void k_misc(const float* __restrict__ W1, const float* __restrict__ W2,
                       const float* __restrict__ b1, const float* __restrict__ b3,
                       const float* __restrict__ head1) {
    int b = blockIdx.x;
    __shared__ float red[256];
    if (b < 16) {
        int fl = threadIdx.x & 63;
        int kg = threadIdx.x >> 6;
        int f = b * 64 + fl;
        float s = 0.f;
        for (int k = kg * 128; k < kg * 128 + 128; k++)
            s += b3[k] * W1[(size_t)k * IN_DIM + f];
        red[threadIdx.x] = s;
        __syncthreads();
        if (threadIdx.x < 64)
            g_u4[b * 64 + threadIdx.x] = red[threadIdx.x] + red[64 + threadIdx.x] +
                                         red[128 + threadIdx.x] + red[192 + threadIdx.x];
    } else if (b == 16) {
        int o = threadIdx.x & 127;
        int kg = threadIdx.x >> 7;
        float s = 0.f;
        for (int k = kg * 256; k < kg * 256 + 256; k++)
            s += W2[(size_t)o * HID_DIM + k] * b1[k];
        red[threadIdx.x] = s;
        __syncthreads();
        if (threadIdx.x < 128)
            g_u2[threadIdx.x] = red[threadIdx.x] + red[128 + threadIdx.x];
    } else {
        for (int idx = threadIdx.x; idx < OUT_DIM * OUT_DIM; idx += 256) {
            int r = idx >> 7, c = idx & 127;
            g_Hth[(size_t)c * OUT_DIM + r] = __float2half(head1[idx]);
        }
    }
}

// ---------------------------------------------------------------------------
// W21 = W2 @ W1 (fp32 FFMA, K=512) -> g_W21 fp32 + g_W21h half.
// grid (IN_DIM/128, 4), BM=32, BN=128, BK=8, 256 threads (32 CTAs).
// ---------------------------------------------------------------------------
__global__ __launch_bounds__(256)
void k_w21(const float* __restrict__ A, const float* __restrict__ B) {
    __shared__ float As[8][32];
    __shared__ float Bs[8][128];
    const int bx = blockIdx.x;
    const int by = blockIdx.y;
    const int tid = threadIdx.x;
    const int tcol = tid % 16;
    const int trow = tid / 16;

    float acc[2][8];
#pragma unroll
    for (int i = 0; i < 2; i++)
#pragma unroll
        for (int j = 0; j < 8; j++) acc[i][j] = 0.0f;

    for (int k0 = 0; k0 < HID_DIM; k0 += 8) {
        if (tid < 64) {
            int aRow = tid >> 1;             // 0..31
            int aCol = (tid & 1) << 2;       // 0 or 4
            int m = by * 32 + aRow;
            float4 av = *(const float4*)(A + (size_t)m * HID_DIM + k0 + aCol);
            As[aCol + 0][aRow] = av.x;
            As[aCol + 1][aRow] = av.y;
            As[aCol + 2][aRow] = av.z;
            As[aCol + 3][aRow] = av.w;
        }
        {
            int kk = tid >> 5;
            int nn = (tid & 31) << 2;
            float4 bv = *(const float4*)(B + (size_t)(k0 + kk) * IN_DIM + bx * 128 + nn);
            *(float4*)&Bs[kk][nn] = bv;
        }
        __syncthreads();
#pragma unroll
        for (int k = 0; k < 8; k++) {
            float ra[2], rb[8];
#pragma unroll
            for (int i = 0; i < 2; i++) ra[i] = As[k][trow * 2 + i];
#pragma unroll
            for (int j = 0; j < 8; j++) rb[j] = Bs[k][tcol * 8 + j];
#pragma unroll
            for (int i = 0; i < 2; i++)
#pragma unroll
                for (int j = 0; j < 8; j++) acc[i][j] += ra[i] * rb[j];
        }
        __syncthreads();
    }
#pragma unroll
    for (int i = 0; i < 2; i++) {
        int m = by * 32 + trow * 2 + i;
#pragma unroll
        for (int j = 0; j < 8; j++) {
            int col = bx * 128 + tcol * 8 + j;
            g_W21[(size_t)m * IN_DIM + col]  = acc[i][j];
            g_W21h[(size_t)m * IN_DIM + col] = __float2half(acc[i][j]);
        }
    }
}

// ---------------------------------------------------------------------------
// HW21 = head1 @ W21 [128,1024] (fp32 FFMA, K=128) -> g_HW21th half transposed.
// grid (IN_DIM/128, 4), BM=32 (same widened layout; off critical path).
// ---------------------------------------------------------------------------
__global__ __launch_bounds__(256)
void k_hw21(const float* __restrict__ head1) {
    __shared__ float As[8][32];
    __shared__ float Bs[8][128];
    const int bx = blockIdx.x;
    const int by = blockIdx.y;
    const int tid = threadIdx.x;
    const int tcol = tid % 16;
    const int trow = tid / 16;

    float acc[2][8];
#pragma unroll
    for (int i = 0; i < 2; i++)
#pragma unroll
        for (int j = 0; j < 8; j++) acc[i][j] = 0.0f;

    for (int k0 = 0; k0 < OUT_DIM; k0 += 8) {
        if (tid < 64) {
            int aRow = tid >> 1;
            int aCol = (tid & 1) << 2;
            int m = by * 32 + aRow;
            float4 av = *(const float4*)(head1 + (size_t)m * OUT_DIM + k0 + aCol);
            As[aCol + 0][aRow] = av.x;
            As[aCol + 1][aRow] = av.y;
            As[aCol + 2][aRow] = av.z;
            As[aCol + 3][aRow] = av.w;
        }
        {
            int kk = tid >> 5;
            int nn = (tid & 31) << 2;
            float4 bv = *(const float4*)(g_W21 + (size_t)(k0 + kk) * IN_DIM + bx * 128 + nn);
            *(float4*)&Bs[kk][nn] = bv;
        }
        __syncthreads();
#pragma unroll
        for (int k = 0; k < 8; k++) {
            float ra[2], rb[8];
#pragma unroll
            for (int i = 0; i < 2; i++) ra[i] = As[k][trow * 2 + i];
#pragma unroll
            for (int j = 0; j < 8; j++) rb[j] = Bs[k][tcol * 8 + j];
#pragma unroll
            for (int i = 0; i < 2; i++)
#pragma unroll
                for (int j = 0; j < 8; j++) acc[i][j] += ra[i] * rb[j];
        }
        __syncthreads();
    }
#pragma unroll
    for (int i = 0; i < 2; i++) {
        int m = by * 32 + trow * 2 + i;
#pragma unroll
        for (int j = 0; j < 8; j++) {
            int col = bx * 128 + tcol * 8 + j;
            g_HW21th[(size_t)col * OUT_DIM + m] = __float2half(acc[i][j]);
        }
    }
}

// ---------------------------------------------------------------------------
// fp16 tensor-core GEMM (TN form), m16n8k16, register-prefetch pipelined.
//   AMODE: 0 = fp32 ext (cvt), 1 = g_Zh half, 2 = g_Hh half.
//   CH: 1 -> C = g_Th (half); 0 -> C = Cext fp32.
// ---------------------------------------------------------------------------
template <int AMODE, int BSEL, int CH, int CORR4, int BMv>
__global__ __launch_bounds__(256)
void k_mma(int M, int Nn, int K,
           const float* __restrict__ Aext,
           float* __restrict__ Cext,
           const float* __restrict__ bias) {
    constexpr int MT  = BMv / 32;
    constexpr int AR4 = BMv / 32;
    const __half* B = pickB<BSEL>();

    __shared__ __half As[BMv][40];
    __shared__ __half Bs[128][40];

    const int tid  = threadIdx.x;
    const int lane = tid & 31;
    const int wid  = tid >> 5;
    const int g    = lane >> 2;
    const int t    = lane & 3;
    const int wm   = (wid & 1) * (BMv / 2);
    const int wn   = (wid >> 1) * 32;
    const int bx   = blockIdx.x;
    const int by   = blockIdx.y;

    float4 ar[AR4];
    uint4  arh[(BMv + 63) / 64];
    uint4  br4[2];

    const __half* Ah = (AMODE == 1) ? g_Zh : g_Hh;

    auto loadA = [&](int k0) {
        if (AMODE == 0) {
#pragma unroll
            for (int i = 0; i < AR4; i++) {
                int f4 = tid + i * 256;
                int m  = f4 >> 3;
                int kq = (f4 & 7) << 2;
                int gm = by * BMv + m;
                ar[i] = (gm < M) ? *(const float4*)(Aext + (size_t)gm * K + k0 + kq)
                                 : make_float4(0.f, 0.f, 0.f, 0.f);
            }
        } else {
#pragma unroll
            for (int i = 0; i < (BMv + 63) / 64; i++) {
                int u  = tid + i * 256;
                int m  = u >> 2;
                int kq = (u & 3) << 3;
                int gm = by * BMv + m;
                arh[i] = (gm < M) ? *(const uint4*)(Ah + (size_t)gm * K + k0 + kq)
                                  : make_uint4(0, 0, 0, 0);
            }
        }
    };
    auto loadB = [&](int k0) {
#pragma unroll
        for (int i = 0; i < 2; i++) {
            int f4 = tid + i * 256;
            int nn = f4 >> 2;
            int kq = (f4 & 3) << 3;
            br4[i] = *(const uint4*)(B + (size_t)(bx * 128 + nn) * K + k0 + kq);
        }
    };
    auto storeA = [&]() {
        if (AMODE == 0) {
#pragma unroll
            for (int i = 0; i < AR4; i++) {
                int f4 = tid + i * 256;
                int m  = f4 >> 3;
                int kq = (f4 & 7) << 2;
                __half2 h01 = __floats2half2_rn(ar[i].x, ar[i].y);
                __half2 h23 = __floats2half2_rn(ar[i].z, ar[i].w);
                *(__half2*)&As[m][kq]     = h01;
                *(__half2*)&As[m][kq + 2] = h23;
            }
        } else {
#pragma unroll
            for (int i = 0; i < (BMv + 63) / 64; i++) {
                int u  = tid + i * 256;
                int m  = u >> 2;
                int kq = (u & 3) << 3;
                *(uint4*)&As[m][kq] = arh[i];
            }
        }
    };
    auto storeB = [&]() {
#pragma unroll
        for (int i = 0; i < 2; i++) {
            int f4 = tid + i * 256;
            int nn = f4 >> 2;
            int kq = (f4 & 3) << 3;
            *(uint4*)&Bs[nn][kq] = br4[i];
        }
    };

    float c[MT][4][4];
#pragma unroll
    for (int i = 0; i < MT; i++)
#pragma unroll
        for (int j = 0; j < 4; j++)
#pragma unroll
            for (int r = 0; r < 4; r++) c[i][j][r] = 0.0f;

    const int nt = K / 32;
    loadA(0); loadB(0);
    storeA(); storeB();
    __syncthreads();

    for (int it = 0; it < nt; it++) {
        if (it + 1 < nt) { loadA((it + 1) * 32); loadB((it + 1) * 32); }

#pragma unroll
        for (int ks = 0; ks < 2; ks++) {
            unsigned a[MT][4], b[4][2];
            int kb = ks * 16 + 2 * t;
#pragma unroll
            for (int i = 0; i < MT; i++) {
                int mr = wm + i * 16 + g;
                a[i][0] = *(const unsigned*)&As[mr    ][kb    ];
                a[i][1] = *(const unsigned*)&As[mr + 8][kb    ];
                a[i][2] = *(const unsigned*)&As[mr    ][kb + 8];
                a[i][3] = *(const unsigned*)&As[mr + 8][kb + 8];
            }
#pragma unroll
            for (int j = 0; j < 4; j++) {
                int nr = wn + j * 8 + g;
                b[j][0] = *(const unsigned*)&Bs[nr][kb    ];
                b[j][1] = *(const unsigned*)&Bs[nr][kb + 8];
            }
#pragma unroll
            for (int i = 0; i < MT; i++)
#pragma unroll
                for (int j = 0; j < 4; j++) {
                    asm volatile(
                        "mma.sync.aligned.m16n8k16.row.col.f32.f16.f16.f32 "
                        "{%0,%1,%2,%3}, {%4,%5,%6,%7}, {%8,%9}, {%0,%1,%2,%3};"
                        : "+f"(c[i][j][0]), "+f"(c[i][j][1]),
                          "+f"(c[i][j][2]), "+f"(c[i][j][3])
                        : "r"(a[i][0]), "r"(a[i][1]), "r"(a[i][2]), "r"(a[i][3]),
                          "r"(b[j][0]), "r"(b[j][1]));
                }
        }
        __syncthreads();
        if (it + 1 < nt) {
            storeA(); storeB();
            __syncthreads();
        }
    }

#pragma unroll
    for (int j = 0; j < 4; j++) {
        int cn = bx * 128 + wn + j * 8 + t * 2;
        float e0 = bias ? bias[cn]     : 0.0f;
        float e1 = bias ? bias[cn + 1] : 0.0f;
        float u40 = CORR4 ? g_u4[cn]     : 0.0f;
        float u41 = CORR4 ? g_u4[cn + 1] : 0.0f;
#pragma unroll
        for (int i = 0; i < MT; i++) {
            int r0 = by * BMv + wm + i * 16 + g;
            if (r0 < M) {
                float a0 = c[i][j][0] + e0, a1 = c[i][j][1] + e1;
                if (CORR4) { float ci = g_c[r0]; a0 += ci * u40; a1 += ci * u41; }
                if (CH) {
                    __half2 h = __floats2half2_rn(a0, a1);
                    *(__half2*)(g_Th + (size_t)r0 * Nn + cn) = h;
                } else {
                    *(float2*)(Cext + (size_t)r0 * Nn + cn) = make_float2(a0, a1);
                }
            }
            int r1 = r0 + 8;
            if (r1 < M) {
                float a2 = c[i][j][2] + e0, a3 = c[i][j][3] + e1;
                if (CORR4) { float ci = g_c[r1]; a2 += ci * u40; a3 += ci * u41; }
                if (CH) {
                    __half2 h = __floats2half2_rn(a2, a3);
                    *(__half2*)(g_Th + (size_t)r1 * Nn + cn) = h;
                } else {
                    *(float2*)(Cext + (size_t)r1 * Nn + cn) = make_float2(a2, a3);
                }
            }
        }
    }
}

// ---------------------------------------------------------------------------
// Aggregation (warp-per-node CSR gather) over HALF sources, fp32 accumulate.
// MLP-8 unrolled edge loop (avg degree ~9 -> one batch + tail).
// ---------------------------------------------------------------------------
template <int SMODE, int DMODE, int CORR, int WRC>
__global__ __launch_bounds__(256)
void k_agg(float* __restrict__ Dext,
           const float* __restrict__ b,
           int n) {
    int gw = (blockIdx.x * 256 + threadIdx.x) >> 5;
    if (gw >= n) return;
    int lane = threadIdx.x & 31;
    const __half* S = pickhb<SMODE>();

    int beg = g_off[gw];
    int end = g_off[gw + 1];
    float sn = g_sn[gw];
    int lo = lane * 4;
    float4 v = h4f(*(const uint2*)(S + (size_t)gw * OUT_DIM + lo));
    float4 acc = make_float4(sn * v.x, sn * v.y, sn * v.z, sn * v.w);
    float cacc = sn;

    int p = beg;
    for (; p + 8 <= end; p += 8) {
        int2  ee[8];
        uint2 uu[8];
#pragma unroll
        for (int q = 0; q < 8; q++) ee[q] = g_adj[p + q];
#pragma unroll
        for (int q = 0; q < 8; q++)
            uu[q] = *(const uint2*)(S + (size_t)ee[q].x * OUT_DIM + lo);
#pragma unroll
        for (int q = 0; q < 8; q++) {
            float w = __int_as_float(ee[q].y);
            if (WRC) cacc += w;
            float4 u = h4f(uu[q]);
            acc.x += w * u.x; acc.y += w * u.y; acc.z += w * u.z; acc.w += w * u.w;
        }
    }
    for (; p + 4 <= end; p += 4) {
        int2  ee[4];
        uint2 uu[4];
#pragma unroll
        for (int q = 0; q < 4; q++) ee[q] = g_adj[p + q];
#pragma unroll
        for (int q = 0; q < 4; q++)
            uu[q] = *(const uint2*)(S + (size_t)ee[q].x * OUT_DIM + lo);
#pragma unroll
        for (int q = 0; q < 4; q++) {
            float w = __int_as_float(ee[q].y);
            if (WRC) cacc += w;
            float4 u = h4f(uu[q]);
            acc.x += w * u.x; acc.y += w * u.y; acc.z += w * u.z; acc.w += w * u.w;
        }
    }
    for (; p < end; p++) {
        int2 pr = g_adj[p];
        float w = __int_as_float(pr.y);
        if (WRC) cacc += w;
        float4 u = h4f(*(const uint2*)(S + (size_t)pr.x * OUT_DIM + lo));
        acc.x += w * u.x; acc.y += w * u.y; acc.z += w * u.z; acc.w += w * u.w;
    }

    if (WRC && lane == 0) g_c[gw] = cacc;

    if (CORR) {
        float ci = g_c[gw];
        acc.x += ci * g_u2[lo + 0] + b[lo + 0];
        acc.y += ci * g_u2[lo + 1] + b[lo + 1];
        acc.z += ci * g_u2[lo + 2] + b[lo + 2];
        acc.w += ci * g_u2[lo + 3] + b[lo + 3];
    }

    if (DMODE == 0) {
        *(float4*)(Dext + (size_t)gw * OUT_DIM + lo) = acc;
        *(uint2*)(g_Zh + (size_t)gw * OUT_DIM + lo) = f4h(acc);
    } else {
        __half* D = pickhbw<DMODE>();
        *(uint2*)(D + (size_t)gw * OUT_DIM + lo) = f4h(acc);
    }
}

// ---------------------------------------------------------------------------
static inline int ceil_div(int a, int b) { return (a + b - 1) / b; }

extern "C" void kernel_launch(void* const* d_in, const int* in_sizes, int n_in,
                              void* d_out, int out_size) {
    const float* features = (const float*)d_in[0];
    const void*  edge_idx = d_in[1];
    const float* W1       = (const float*)d_in[2];
    const float* b1       = (const float*)d_in[3];
    const float* W2       = (const float*)d_in[4];
    const float* b2       = (const float*)d_in[5];
    const float* b3       = (const float*)d_in[6];
    const float* b4       = (const float*)d_in[7];
    const float* head1    = (const float*)d_in[8];

    const int n = in_sizes[0] / IN_DIM;
    const int e = in_sizes[1] / 2;

    float* out = (float*)d_out;
    float* z_out  = out;
    float* h2_out = out + (size_t)n * OUT_DIM;
    float* h4_out = out + (size_t)n * OUT_DIM * 2;

    const int TPB = 256;
    dim3 blk(256);
    int aggb = ceil_div(n * 32, TPB);

    static cudaStream_t s1 = nullptr;
    static cudaEvent_t evFork = nullptr, evP = nullptr, evAux = nullptr,
                       evHW = nullptr, evH2 = nullptr, evZ = nullptr;
    if (s1 == nullptr) {
        cudaStreamCreateWithFlags(&s1, cudaStreamNonBlocking);
        cudaEventCreateWithFlags(&evFork, cudaEventDisableTiming);
        cudaEventCreateWithFlags(&evP,    cudaEventDisableTiming);
        cudaEventCreateWithFlags(&evAux,  cudaEventDisableTiming);
        cudaEventCreateWithFlags(&evHW,   cudaEventDisableTiming);
        cudaEventCreateWithFlags(&evH2,   cudaEventDisableTiming);
        cudaEventCreateWithFlags(&evZ,    cudaEventDisableTiming);
    }

    // ---- fork ----
    cudaEventRecord(evFork, 0);
    cudaStreamWaitEvent(s1, evFork, 0);

    // s1: w21 -> P (critical) ; then misc, hw21 (off critical path)
    {
        dim3 grid(IN_DIM / 128, 4);     // 32 CTAs
        k_w21<<<grid, blk, 0, s1>>>(W2, W1);
    }
    {
        dim3 grid(1, ceil_div(n, 64));  // P = X @ W21^T -> g_Th (half)
        k_mma<0, 3, 1, 0, 64><<<grid, blk, 0, s1>>>(n, OUT_DIM, IN_DIM, features,
                                                    nullptr, nullptr);
    }
    cudaEventRecord(evP, s1);
    k_misc<<<18, 256, 0, s1>>>(W1, W2, b1, b3, head1);
    cudaEventRecord(evAux, s1);
    {
        dim3 grid(IN_DIM / 128, 4);     // 32 CTAs
        k_hw21<<<grid, blk, 0, s1>>>(head1);
    }
    cudaEventRecord(evHW, s1);

    // s0: CSR chain (g_cnt zero at entry; k_scan re-zeros it)
    k_count<<<ceil_div(e, TPB), TPB>>>(edge_idx, e, n);
    k_scan<<<1, 1024>>>(n);
    k_fill<<<ceil_div(e, TPB), TPB>>>(edge_idx, e, n);

    cudaStreamWaitEvent(0, evP, 0);

    // ---- S1 = Ahat P -> g_Hh (computes c) ----
    k_agg<1, 2, 0, 1><<<aggb, blk>>>(nullptr, nullptr, n);

    // ---- h2 = Ahat S1 + c(x)u2 + b2 -> h2_out (+half copy g_Zh) ----
    cudaStreamWaitEvent(0, evAux, 0);
    k_agg<2, 0, 1, 0><<<aggb, blk>>>(h2_out, b2, n);
    cudaEventRecord(evH2, 0);

    // s1: z = (h2 half) @ head1 -> z_out (parallel with aggs below)
    cudaStreamWaitEvent(s1, evH2, 0);
    {
        dim3 grid(1, ceil_div(n, 64));
        k_mma<1, 5, 0, 0, 64><<<grid, blk, 0, s1>>>(n, OUT_DIM, OUT_DIM, nullptr,
                                                    z_out, nullptr);
    }
    cudaEventRecord(evZ, s1);

    // ---- S2 = Ahat h2 -> g_Th ; R = Ahat S2 -> g_Hh ----
    k_agg<3, 1, 0, 0><<<aggb, blk>>>(nullptr, nullptr, n);
    k_agg<1, 2, 0, 0><<<aggb, blk>>>(nullptr, nullptr, n);

    // ---- h4 = R @ HW21 + c(x)u4 + b4 -> h4_out ----
    cudaStreamWaitEvent(0, evHW, 0);
    {
        dim3 grid(IN_DIM / 128, ceil_div(n, 128));
        k_mma<2, 4, 0, 1, 128><<<grid, blk>>>(n, IN_DIM, OUT_DIM, nullptr,
                                              h4_out, b4);
    }

    cudaStreamWaitEvent(0, evZ, 0);

    (void)n_in; (void)out_size;
}